// round 9
// baseline (speedup 1.0000x reference)
#include <cuda_runtime.h>
#include <cuda_bf16.h>

#define BB 32
#define TT 400
#define DD 1024
#define VV 5000
#define LL 100
#define L1 101
#define NEGBIG -1e30f
#define NBLK 148
#define SMSZ 202752
#define BIG_SMEM 110592

__device__ __align__(16) __nv_bfloat16 g_hsb [BB * TT * DD];
__device__ __align__(16) __nv_bfloat16 g_preb[BB * TT * DD];
__device__ __align__(16) __nv_bfloat16 g_eysb[L1 * BB * DD];
__device__ __align__(16) __nv_bfloat16 g_Wencb[DD * DD];
__device__ __align__(16) __nv_bfloat16 g_Wdecb[DD * DD];
__device__ __align__(16) __nv_bfloat16 g_Woutb[VV * 2048];
__device__ __align__(16) __nv_bfloat16 g_Wc0e[4096 * 1024];
__device__ __align__(16) __nv_bfloat16 g_Wc0x[4096 * 2048];
__device__ __align__(16) __nv_bfloat16 g_Wc1r[4096 * 2048];
__device__ __align__(16) float g_bs0r[4096];
__device__ __align__(16) float g_bs1r[4096];
__device__ __align__(16) float g_emb0[(long long)L1 * BB * 4096];
__device__ __align__(16) __nv_bfloat16 g_dqb[BB * DD];
__device__ __align__(16) __nv_bfloat16 g_attb[BB * DD];
__device__ __align__(16) __nv_bfloat16 g_z0s[2][BB * DD];
__device__ __align__(16) __nv_bfloat16 g_z1s[2][BB * DD];
__device__ __align__(16) float g_c0[BB * DD];
__device__ __align__(16) float g_c1[BB * DD];
__device__ __align__(16) float g_pc[84 * 1024];
__device__ __align__(16) float g_ms[168];
__device__ unsigned g_cmb[32];
__device__ __align__(16) __nv_bfloat16 g_zallb[L1 * BB * 2048];
__device__ __align__(16) float g_yall[(long long)L1 * BB * VV];
__device__ float g_loss;
__device__ int g_i64;
__device__ unsigned g_arrive;
__device__ unsigned g_release;

__device__ __forceinline__ float sigm(float x) { return 1.0f / (1.0f + expf(-x)); }
__device__ __forceinline__ int read_ys(const void* ys, int i) {
    return g_i64 ? (int)((const long long*)ys)[i] : ((const int*)ys)[i];
}
__device__ __forceinline__ unsigned sptr(const void* p) {
    unsigned r;
    asm("{.reg .u64 t; cvta.to.shared.u64 t, %1; cvt.u32.u64 %0, t;}" : "=r"(r) : "l"(p));
    return r;
}
__device__ __forceinline__ void cpa16(unsigned s, const void* g) {
    asm volatile("cp.async.cg.shared.global [%0], [%1], 16;" :: "r"(s), "l"(g));
}
#define CP_COMMIT asm volatile("cp.async.commit_group;")
#define CP_WAIT2  asm volatile("cp.async.wait_group 2;")
#define CP_WAIT1  asm volatile("cp.async.wait_group 1;")

__device__ __forceinline__ unsigned pack2(float a, float b) {
    __nv_bfloat162 p = __floats2bfloat162_rn(a, b);
    return *(unsigned*)&p;
}

// ---------------------------------------------------------------- fused prologue
__global__ void k_prep_all(
    const float* __restrict__ hs, const float* __restrict__ embed,
    const float* __restrict__ Wenc, const float* __restrict__ Wdec,
    const float* __restrict__ Wout,
    const float* __restrict__ Wih0, const float* __restrict__ Whh0,
    const float* __restrict__ Wih1, const float* __restrict__ Whh1,
    const float* __restrict__ bih0, const float* __restrict__ bhh0,
    const float* __restrict__ bih1, const float* __restrict__ bhh1,
    const void* __restrict__ ys)
{
    __shared__ int s_i64;
    const int tid = threadIdx.x;
    if (tid == 0) {
        const int* w = (const int*)ys;
        int f = 1;
        for (int j = 1; j < 64; j += 2) if (w[j] != 0) f = 0;
        s_i64 = f;
    }
    __syncthreads();
    const int i64 = s_i64;
    const long long gi = (long long)blockIdx.x * blockDim.x + tid;
    const long long gn = (long long)gridDim.x * blockDim.x;

    {
        __nv_bfloat16 z = __float2bfloat16(0.f);
        for (long long j = gi; j < BB * DD; j += gn) {
            g_c0[j] = 0.f; g_c1[j] = 0.f;
            g_z0s[0][j] = z; g_z0s[1][j] = z;
            g_z1s[0][j] = z; g_z1s[1][j] = z;
        }
        for (long long j = gi; j < 4096; j += gn) {
            int u = (int)j >> 2, gate = (int)j & 3;
            int orow = gate * 1024 + u;
            g_bs0r[j] = bih0[orow] + bhh0[orow];
            g_bs1r[j] = bih1[orow] + bhh1[orow];
        }
        if (gi < 32) g_cmb[gi] = 0u;
        if (gi == 0) { g_loss = 0.f; g_arrive = 0u; g_release = 0u; g_i64 = i64; }
    }
    {
        const float4* s = (const float4*)hs;
        uint4* d = (uint4*)g_hsb;
        for (long long j = gi; j < 1638400LL; j += gn) {
            float4 a = s[2 * j], b = s[2 * j + 1];
            d[j] = make_uint4(pack2(a.x, a.y), pack2(a.z, a.w), pack2(b.x, b.y), pack2(b.z, b.w));
        }
    }
    {
        const float4* s = (const float4*)Wenc;
        uint4* d = (uint4*)g_Wencb;
        for (long long j = gi; j < 131072LL; j += gn) {
            float4 a = s[2 * j], b = s[2 * j + 1];
            d[j] = make_uint4(pack2(a.x, a.y), pack2(a.z, a.w), pack2(b.x, b.y), pack2(b.z, b.w));
        }
    }
    {
        const float4* s = (const float4*)Wdec;
        uint4* d = (uint4*)g_Wdecb;
        for (long long j = gi; j < 131072LL; j += gn) {
            float4 a = s[2 * j], b = s[2 * j + 1];
            d[j] = make_uint4(pack2(a.x, a.y), pack2(a.z, a.w), pack2(b.x, b.y), pack2(b.z, b.w));
        }
    }
    {
        const float4* s = (const float4*)Wout;
        uint4* d = (uint4*)g_Woutb;
        for (long long j = gi; j < 1280000LL; j += gn) {
            float4 a = s[2 * j], b = s[2 * j + 1];
            d[j] = make_uint4(pack2(a.x, a.y), pack2(a.z, a.w), pack2(b.x, b.y), pack2(b.z, b.w));
        }
    }
    {
        for (long long it = gi; it < 413696LL; it += gn) {
            int row = (int)(it >> 7), col = (int)(it & 127);
            int l = row >> 5, b = row & 31;
            int tok = 4999;
            if (l > 0) {
                int idx = b * LL + l - 1;
                tok = i64 ? (int)((const long long*)ys)[idx] : ((const int*)ys)[idx];
            }
            float4 v = ((const float4*)(embed + (long long)tok * 1024))[col];
            ((uint2*)(g_eysb + (long long)row * 1024))[col] = make_uint2(pack2(v.x, v.y), pack2(v.z, v.w));
        }
    }
    {
        for (long long j4 = gi; j4 < 1048576LL; j4 += gn) {
            long long j = j4 * 4;
            int r = (int)(j >> 10), c = (int)(j & 1023);
            long long orow = (r & 3) * 1024 + (r >> 2);
            float4 v = *(const float4*)(Wih0 + orow * 2048 + c);
            *(uint2*)(g_Wc0e + j) = make_uint2(pack2(v.x, v.y), pack2(v.z, v.w));
        }
    }
    {
        for (long long j4 = gi; j4 < 2097152LL; j4 += gn) {
            long long j = j4 * 4;
            int r = (int)(j >> 11), c = (int)(j & 2047);
            long long orow = (r & 3) * 1024 + (r >> 2);
            float4 v = (c < 1024) ? *(const float4*)(Wih0 + orow * 2048 + 1024 + c)
                                  : *(const float4*)(Whh0 + orow * 1024 + (c - 1024));
            *(uint2*)(g_Wc0x + j) = make_uint2(pack2(v.x, v.y), pack2(v.z, v.w));
        }
    }
    {
        for (long long j4 = gi; j4 < 2097152LL; j4 += gn) {
            long long j = j4 * 4;
            int r = (int)(j >> 11), c = (int)(j & 2047);
            long long orow = (r & 3) * 1024 + (r >> 2);
            float4 v = (c < 1024) ? *(const float4*)(Wih1 + orow * 1024 + c)
                                  : *(const float4*)(Whh1 + orow * 1024 + (c - 1024));
            *(uint2*)(g_Wc1r + j) = make_uint2(pack2(v.x, v.y), pack2(v.z, v.w));
        }
    }
}

__device__ __forceinline__ void mma_bf16(float* d, const unsigned* a, const unsigned* b) {
    asm volatile(
        "mma.sync.aligned.m16n8k16.row.col.f32.bf16.bf16.f32 "
        "{%0,%1,%2,%3}, {%4,%5,%6,%7}, {%8,%9}, {%0,%1,%2,%3};\n"
        : "+f"(d[0]), "+f"(d[1]), "+f"(d[2]), "+f"(d[3])
        : "r"(a[0]), "r"(a[1]), "r"(a[2]), "r"(a[3]), "r"(b[0]), "r"(b[1]));
}

// ---------------------------------------------------------------- big GEMM
#define BKP 72
__device__ __forceinline__ void issue_big(
    char* smb, int slot, int k0,
    const __nv_bfloat16* A, const __nv_bfloat16* B,
    int M, int N, int K, int m0, int n0)
{
    __nv_bfloat16* smA = (__nv_bfloat16*)smb + slot * (2 * 128 * BKP);
    __nv_bfloat16* smB = smA + 128 * BKP;
    const int tid = threadIdx.x;
#pragma unroll
    for (int j = 0; j < 4; j++) {
        int idx = tid + j * 256;
        int r = idx >> 3, c = (idx & 7) * 8;
        int m = m0 + r; if (m >= M) m = 0;
        cpa16(sptr(smA + r * BKP + c), A + (long long)m * K + k0 + c);
        int n = n0 + r; if (n >= N) n = 0;
        cpa16(sptr(smB + r * BKP + c), B + (long long)n * K + k0 + c);
    }
}

template <int EPI>
__global__ __launch_bounds__(256) void mma_big(
    const __nv_bfloat16* __restrict__ A, const __nv_bfloat16* __restrict__ B,
    const float* __restrict__ bias, float* __restrict__ Cf,
    __nv_bfloat16* __restrict__ Cb, int M, int N, int K)
{
    extern __shared__ char smb[];
    const int tid = threadIdx.x, lane = tid & 31, wid = tid >> 5;
    const int wm = wid >> 1, wn = wid & 1;
    const int m0 = blockIdx.y * 128, n0 = blockIdx.x * 128;
    const int g = lane >> 2, tg = lane & 3;
    const int S = K >> 6;

    float acc[2][8][4];
#pragma unroll
    for (int a = 0; a < 2; a++)
#pragma unroll
        for (int b = 0; b < 8; b++)
#pragma unroll
            for (int c = 0; c < 4; c++) acc[a][b][c] = 0.f;

    issue_big(smb, 0, 0, A, B, M, N, K, m0, n0); CP_COMMIT;
    if (S > 1) issue_big(smb, 1, 64, A, B, M, N, K, m0, n0);
    CP_COMMIT;

    for (int si = 0; si < S; si++) {
        CP_WAIT1;
        __syncthreads();
        if (si + 2 < S) issue_big(smb, (si + 2) % 3, (si + 2) << 6, A, B, M, N, K, m0, n0);
        CP_COMMIT;
        __nv_bfloat16 (*As)[BKP] = (__nv_bfloat16(*)[BKP])((__nv_bfloat16*)smb + (si % 3) * (2 * 128 * BKP));
        __nv_bfloat16 (*Bs)[BKP] = (__nv_bfloat16(*)[BKP])((__nv_bfloat16*)smb + (si % 3) * (2 * 128 * BKP) + 128 * BKP);
#pragma unroll
        for (int kt = 0; kt < 4; kt++) {
            const int c0 = kt * 16 + tg * 2;
            unsigned af[2][4];
#pragma unroll
            for (int mt = 0; mt < 2; mt++) {
                int r = wm * 32 + mt * 16 + g;
                af[mt][0] = *(const unsigned*)&As[r][c0];
                af[mt][1] = *(const unsigned*)&As[r + 8][c0];
                af[mt][2] = *(const unsigned*)&As[r][c0 + 8];
                af[mt][3] = *(const unsigned*)&As[r + 8][c0 + 8];
            }
#pragma unroll
            for (int nt = 0; nt < 8; nt++) {
                int n = wn * 64 + nt * 8 + g;
                unsigned bf[2];
                bf[0] = *(const unsigned*)&Bs[n][c0];
                bf[1] = *(const unsigned*)&Bs[n][c0 + 8];
                mma_bf16(acc[0][nt], af[0], bf);
                mma_bf16(acc[1][nt], af[1], bf);
            }
        }
    }

#pragma unroll
    for (int mt = 0; mt < 2; mt++) {
#pragma unroll
        for (int nt = 0; nt < 8; nt++) {
            int r = m0 + wm * 32 + mt * 16 + g;
            int c = n0 + wn * 64 + nt * 8 + tg * 2;
            float* a = acc[mt][nt];
            if (EPI == 0) {
                float b0 = (c < N) ? bias[c] : 0.f;
                float b1 = (c + 1 < N) ? bias[c + 1] : 0.f;
                if (r < M) {
                    if (c < N)     Cf[(long long)r * N + c]     = a[0] + b0;
                    if (c + 1 < N) Cf[(long long)r * N + c + 1] = a[1] + b1;
                }
                if (r + 8 < M) {
                    if (c < N)     Cf[(long long)(r + 8) * N + c]     = a[2] + b0;
                    if (c + 1 < N) Cf[(long long)(r + 8) * N + c + 1] = a[3] + b1;
                }
            } else {
                float b0 = bias[c], b1 = bias[c + 1];
                __nv_bfloat162 v0 = __floats2bfloat162_rn(tanhf(a[0] + b0), tanhf(a[1] + b1));
                __nv_bfloat162 v1 = __floats2bfloat162_rn(tanhf(a[2] + b0), tanhf(a[3] + b1));
                *(__nv_bfloat162*)(Cb + (long long)r * N + c) = v0;
                *(__nv_bfloat162*)(Cb + (long long)(r + 8) * N + c) = v1;
            }
        }
    }
}

// ---------------------------------------------------------------- barrier
__device__ __forceinline__ void gbar(int e) {
    __syncthreads();
    if (threadIdx.x == 0) {
        __threadfence();
        unsigned old = atomicAdd(&g_arrive, 1u);
        if (old == (unsigned)e * NBLK + (NBLK - 1)) {
            atomicExch(&g_release, (unsigned)(e + 1));
        } else {
            unsigned r;
            do { asm volatile("ld.global.cg.u32 %0, [%1];" : "=r"(r) : "l"(&g_release)); }
            while (r < (unsigned)(e + 1));
        }
        __threadfence();
    }
    __syncthreads();
}

// ---------------------------------------------------------------- tile GEMM (NT=8 everywhere)
template <int AKIND, int NT>
__device__ __forceinline__ void issue_chunk(
    char* smraw, int slot, int kc, int K,
    const __nv_bfloat16* A0, const __nv_bfloat16* A1,
    const __nv_bfloat16* B, int n0)
{
    constexpr int ASZ = 32 * 264;
    constexpr int STE = ASZ + NT * 8 * 264;
    __nv_bfloat16* smA = (__nv_bfloat16*)smraw + slot * STE;
    __nv_bfloat16* smB = smA + ASZ;
    const int tid = threadIdx.x;
    const int kbase = kc << 8;
    const int region = kbase >> 10;
    const int koff = kbase & 1023;
#pragma unroll
    for (int j = 0; j < 4; j++) {
        int u = tid + j * 256;
        int r = u >> 5, c = (u & 31) << 3;
        const __nv_bfloat16* src;
        if (AKIND == 0) src = A0 + r * 1024 + kbase + c;
        else src = (region == 0 ? A0 : A1) + r * 1024 + koff + c;
        cpa16(sptr(smA + r * 264 + c), src);
    }
#pragma unroll
    for (int j = 0; j < NT; j++) {
        int u = tid + j * 256;
        int r = u >> 5, c = (u & 31) << 3;
        cpa16(sptr(smB + r * 264 + c), B + (long long)(n0 + r) * K + kbase + c);
    }
}

template <int AKIND, int EPI, int NT, bool ZALL, bool HASEB>
__device__ void gtile(char* smraw, int n0, int K,
                      const __nv_bfloat16* __restrict__ B, const float* __restrict__ bias,
                      const __nv_bfloat16* A0, const __nv_bfloat16* A1,
                      __nv_bfloat16* outb, float* cst, __nv_bfloat16* znew,
                      __nv_bfloat16* zallp, int step, const float* eb)
{
    constexpr int ASZ = 32 * 264;
    constexpr int STE = ASZ + NT * 8 * 264;
    constexpr int NW = 32 * NT * 8;
    const int tid = threadIdx.x, lane = tid & 31, wid = tid >> 5;
    const int g = lane >> 2, tg = lane & 3;
    const int S = K >> 8;

    float acc[2][NT][4];
#pragma unroll
    for (int a = 0; a < 2; a++)
#pragma unroll
        for (int b = 0; b < NT; b++)
#pragma unroll
            for (int c = 0; c < 4; c++) acc[a][b][c] = 0.f;

#pragma unroll
    for (int st = 0; st < 3; st++) {
        if (st < S) issue_chunk<AKIND, NT>(smraw, st, st, K, A0, A1, B, n0);
        CP_COMMIT;
    }

    for (int si = 0; si < S; si++) {
        CP_WAIT2;
        __syncthreads();
        int nx = si + 3;
        if (nx < S) issue_chunk<AKIND, NT>(smraw, nx & 3, nx, K, A0, A1, B, n0);
        CP_COMMIT;
        __nv_bfloat16 (*As)[264] = (__nv_bfloat16(*)[264])((__nv_bfloat16*)smraw + (si & 3) * STE);
        __nv_bfloat16 (*Bs)[264] = (__nv_bfloat16(*)[264])((__nv_bfloat16*)smraw + (si & 3) * STE + ASZ);
#pragma unroll
        for (int ks = 0; ks < 2; ks++) {
            const int c0 = wid * 32 + ks * 16 + tg * 2;
            unsigned af[2][4];
#pragma unroll
            for (int mt = 0; mt < 2; mt++) {
                int r = mt * 16 + g;
                af[mt][0] = *(const unsigned*)&As[r][c0];
                af[mt][1] = *(const unsigned*)&As[r + 8][c0];
                af[mt][2] = *(const unsigned*)&As[r][c0 + 8];
                af[mt][3] = *(const unsigned*)&As[r + 8][c0 + 8];
            }
#pragma unroll
            for (int nt = 0; nt < NT; nt++) {
                int n = nt * 8 + g;
                unsigned bf[2];
                bf[0] = *(const unsigned*)&Bs[n][c0];
                bf[1] = *(const unsigned*)&Bs[n][c0 + 8];
                mma_bf16(acc[0][nt], af[0], bf);
                mma_bf16(acc[1][nt], af[1], bf);
            }
        }
    }
    __syncthreads();

    float* Pred = (float*)smraw;
    {
        int base = wid * NW;
#pragma unroll
        for (int mt = 0; mt < 2; mt++)
#pragma unroll
            for (int nt = 0; nt < NT; nt++) {
                int r = mt * 16 + g, cl = nt * 8 + tg * 2;
                Pred[base + r * (NT * 8) + cl]           = acc[mt][nt][0];
                Pred[base + r * (NT * 8) + cl + 1]       = acc[mt][nt][1];
                Pred[base + (r + 8) * (NT * 8) + cl]     = acc[mt][nt][2];
                Pred[base + (r + 8) * (NT * 8) + cl + 1] = acc[mt][nt][3];
            }
    }
    __syncthreads();

    if (EPI == 0) {
        for (int o = tid; o < NW; o += 256) {
            int r = o / (NT * 8), c = o % (NT * 8);
            float sum = 0.f;
#pragma unroll
            for (int w = 0; w < 8; w++) sum += Pred[w * NW + o];
            outb[r * 1024 + n0 + c] = __float2bfloat16(tanhf(sum + bias[n0 + c]));
        }
    } else {
        // tile covers NT*8 gate-cols = 2*NT units per row; 32 b rows.
        for (int it = tid; it < 32 * 2 * NT; it += 256) {
            int b = it / (2 * NT), ul = it % (2 * NT);
            float gv[4];
#pragma unroll
            for (int gate = 0; gate < 4; gate++) {
                int col = ul * 4 + gate;
                float sum = 0.f;
#pragma unroll
                for (int w = 0; w < 8; w++) sum += Pred[w * NW + b * (NT * 8) + col];
                float bb = HASEB ? eb[b * 4096 + n0 + col] : bias[n0 + col];
                gv[gate] = sum + bb;
            }
            int u = (n0 >> 2) + ul;
            int gid = b * 1024 + u;
            float cv = sigm(gv[1]) * cst[gid] + sigm(gv[0]) * tanhf(gv[2]);
            float h = sigm(gv[3]) * tanhf(cv);
            cst[gid] = cv;
            znew[gid] = __float2bfloat16(h);
            if (ZALL) zallp[(long long)(step * 32 + b) * 2048 + u] = __float2bfloat16(h);
        }
    }
    __syncthreads();
}

// ---------------------------------------------------------------- attention (84 blocks: bid 64..147)
// b<20: 3 chunks (136/132/132); b>=20: 2 chunks (200/200)
__device__ void phase_epc(char* smraw, int s, const int* __restrict__ hlens) {
    const int aid = blockIdx.x - 64;
    int b, t0, tlen, ncs, base;
    if (aid < 60) {
        b = aid / 3; int ch = aid - b * 3; ncs = 3; base = b * 3;
        t0 = (ch == 0) ? 0 : (ch == 1 ? 136 : 268);
        tlen = (ch == 0) ? 136 : 132;
    } else {
        int u = aid - 60; b = 20 + (u >> 1); int ch = u & 1; ncs = 2; base = 60 + (b - 20) * 2;
        t0 = ch * 200; tlen = 200;
    }

    const int tid = threadIdx.x, lane = tid & 31, wid = tid >> 5;
    float* dqs = (float*)smraw;
    float* ws  = dqs + 1024;      // 200
    float* red = ws + 200;        // 256
    float* pcr = red + 256;       // 8192
    int*   flg = (int*)(pcr + 8192);

    const uint4* dqp = (const uint4*)(g_dqb + b * 1024);
    for (int j = tid; j < 128; j += 256) {
        uint4 v = __ldcg(dqp + j);
        const __nv_bfloat162* h = (const __nv_bfloat162*)&v;
#pragma unroll
        for (int k = 0; k < 4; k++) {
            float2 f = __bfloat1622float2(h[k]);
            dqs[j * 8 + k * 2]     = f.x;
            dqs[j * 8 + k * 2 + 1] = f.y;
        }
    }
    __syncthreads();

    const int hl = hlens[b];
    for (int bs = wid * 2; bs < tlen; bs += 16) {
        const __nv_bfloat16* r1 = g_preb + ((long long)b * 400 + t0 + bs) * 1024 + lane * 8;
        const __nv_bfloat16* r2 = r1 + 1024;
        float a1 = 0.f, a2 = 0.f, a3 = 0.f, a4 = 0.f;
#pragma unroll
        for (int q = 0; q < 4; q++) {
            uint4 v1 = *(const uint4*)(r1 + q * 256);
            uint4 v2 = *(const uint4*)(r2 + q * 256);
            const __nv_bfloat162* h1 = (const __nv_bfloat162*)&v1;
            const __nv_bfloat162* h2 = (const __nv_bfloat162*)&v2;
#pragma unroll
            for (int k = 0; k < 4; k++) {
                float2 d = *(const float2*)(dqs + q * 256 + lane * 8 + k * 2);
                float2 f1 = __bfloat1622float2(h1[k]);
                float2 f2 = __bfloat1622float2(h2[k]);
                a1 = fmaf(f1.x, d.x, a1); a2 = fmaf(f1.y, d.y, a2);
                a3 = fmaf(f2.x, d.x, a3); a4 = fmaf(f2.y, d.y, a4);
            }
        }
        float s1 = a1 + a2, s2 = a3 + a4;
#pragma unroll
        for (int off = 16; off; off >>= 1) {
            s1 += __shfl_xor_sync(0xffffffffu, s1, off);
            s2 += __shfl_xor_sync(0xffffffffu, s2, off);
        }
        if (lane == 0) {
            int t = t0 + bs;
            ws[bs]     = (t < hl)     ? 2.f * s1 : NEGBIG;
            ws[bs + 1] = (t + 1 < hl) ? 2.f * s2 : NEGBIG;
        }
    }
    __syncthreads();

    float lm = NEGBIG;
    for (int i = tid; i < tlen; i += 256) lm = fmaxf(lm, ws[i]);
    red[tid] = lm; __syncthreads();
    for (int st = 128; st; st >>= 1) { if (tid < st) red[tid] = fmaxf(red[tid], red[tid + st]); __syncthreads(); }
    const float m = red[0]; __syncthreads();
    float ls = 0.f;
    for (int i = tid; i < tlen; i += 256) { float w = expf(ws[i] - m); ws[i] = w; ls += w; }
    red[tid] = ls; __syncthreads();
    for (int st = 128; st; st >>= 1) { if (tid < st) red[tid] += red[tid + st]; __syncthreads(); }
    const float sl = red[0];
    __syncthreads();

    float pacc[32];
#pragma unroll
    for (int i = 0; i < 32; i++) pacc[i] = 0.f;
    for (int bs = wid * 2; bs < tlen; bs += 16) {
        float w1 = ws[bs], w2 = ws[bs + 1];
        const __nv_bfloat16* r1 = g_hsb + ((long long)b * 400 + t0 + bs) * 1024 + lane * 8;
        const __nv_bfloat16* r2 = r1 + 1024;
#pragma unroll
        for (int q = 0; q < 4; q++) {
            uint4 v1 = *(const uint4*)(r1 + q * 256);
            uint4 v2 = *(const uint4*)(r2 + q * 256);
            const __nv_bfloat162* h1 = (const __nv_bfloat162*)&v1;
            const __nv_bfloat162* h2 = (const __nv_bfloat162*)&v2;
#pragma unroll
            for (int k = 0; k < 4; k++) {
                float2 f1 = __bfloat1622float2(h1[k]);
                float2 f2 = __bfloat1622float2(h2[k]);
                int o = q * 8 + k * 2;
                pacc[o]     = fmaf(w1, f1.x, fmaf(w2, f2.x, pacc[o]));
                pacc[o + 1] = fmaf(w1, f1.y, fmaf(w2, f2.y, pacc[o + 1]));
            }
        }
    }
#pragma unroll
    for (int q = 0; q < 4; q++)
#pragma unroll
        for (int j = 0; j < 8; j++)
            pcr[wid * 1024 + q * 256 + lane * 8 + j] = pacc[q * 8 + j];
    __syncthreads();
    for (int col = tid; col < 1024; col += 256) {
        float a = 0.f;
#pragma unroll
        for (int w = 0; w < 8; w++) a += pcr[w * 1024 + col];
        g_pc[aid * 1024 + col] = a;
    }
    if (tid == 0) { g_ms[aid * 2] = m; g_ms[aid * 2 + 1] = sl; }
    __syncthreads();

    if (tid == 0) {
        __threadfence();
        unsigned old = atomicAdd(&g_cmb[b], 1u);
        *flg = (old == (unsigned)(s * ncs + ncs - 1)) ? 1 : 0;
    }
    __syncthreads();
    if (*flg) {
        float mi[3], si[3];
        for (int i = 0; i < ncs; i++) {
            mi[i] = __ldcg(&g_ms[(base + i) * 2]);
            si[i] = __ldcg(&g_ms[(base + i) * 2 + 1]);
        }
        float M = NEGBIG;
        for (int i = 0; i < ncs; i++) M = fmaxf(M, mi[i]);
        float sc[3], Ssum = 0.f;
        for (int i = 0; i < ncs; i++) { sc[i] = expf(mi[i] - M); Ssum += sc[i] * si[i]; }
        float inv = 1.f / Ssum;
        for (int col = tid; col < 1024; col += 256) {
            float a = 0.f;
            for (int i = 0; i < ncs; i++) a += sc[i] * __ldcg(&g_pc[(base + i) * 1024 + col]);
            __nv_bfloat16 v = __float2bfloat16(a * inv);
            g_attb[b * 1024 + col] = v;
            g_zallb[((long long)s * 32 + b) * 2048 + 1024 + col] = v;
        }
    }
    __syncthreads();
}

// ---------------------------------------------------------------- main loop
// Phase A: dq(s) on 16 blocks. Phase B: g1(s-1) on 0..63 || attn(s) on 64..147.
// Phase C: g0(s) on 0..63.
__global__ void __launch_bounds__(256, 1) k_loop(const int* __restrict__ hlens,
                                                 const float* __restrict__ bdec) {
    extern __shared__ char sm[];
    const int bid = blockIdx.x;
    int ep = 0;

    for (int s = 0; s <= 101; s++) {
        const int p = s & 1;
        // Phase A: dq(s)
        if (s <= 100 && bid < 16) {
            gtile<0, 0, 8, false, false>(sm, bid * 64, 1024, g_Wdecb, bdec,
                                         g_z0s[p], nullptr,
                                         g_dqb, nullptr, nullptr, nullptr, s, nullptr);
        }
        gbar(ep); ep++;

        // Phase B: g1(s-1) || attn(s)
        if (bid < 64) {
            if (s >= 1)
                gtile<2, 1, 8, true, false>(sm, bid * 64, 2048, g_Wc1r, g_bs1r,
                                            g_z0s[p], g_z1s[1 - p],
                                            nullptr, g_c1, g_z1s[p], g_zallb, s - 1, nullptr);
        } else {
            if (s <= 100) phase_epc(sm, s, hlens);
        }
        gbar(ep); ep++;
        if (s == 101) break;

        // Phase C: g0(s)
        if (bid < 64) {
            gtile<2, 1, 8, false, true>(sm, bid * 64, 2048, g_Wc0x, nullptr,
                                        g_attb, g_z0s[p],
                                        nullptr, g_c0, g_z0s[1 - p], nullptr, s,
                                        g_emb0 + (long long)s * 32 * 4096);
        }
        gbar(ep); ep++;
    }
}

// ---------------------------------------------------------------- CE
__global__ void k_ce(const void* __restrict__ ys) {
    int r = blockIdx.x;
    int l = r / BB, b = r % BB;
    const float* y = g_yall + (long long)r * VV;
    __shared__ float red[256];
    int tid = threadIdx.x;
    float lm = NEGBIG;
    for (int v = tid; v < VV; v += 256) lm = fmaxf(lm, y[v]);
    red[tid] = lm; __syncthreads();
    for (int s = 128; s > 0; s >>= 1) { if (tid < s) red[tid] = fmaxf(red[tid], red[tid + s]); __syncthreads(); }
    float m = red[0]; __syncthreads();
    float ls = 0.f;
    for (int v = tid; v < VV; v += 256) ls += expf(y[v] - m);
    red[tid] = ls; __syncthreads();
    for (int s = 128; s > 0; s >>= 1) { if (tid < s) red[tid] += red[tid + s]; __syncthreads(); }
    if (tid == 0) {
        int tgt = (l < LL) ? read_ys(ys, b * LL + l) : 4999;
        atomicAdd(&g_loss, logf(red[0]) + m - y[tgt]);
    }
}

__global__ void k_fin(float* out) {
    out[0] = g_loss * ((float)LL / (float)(L1 * BB));
}

// ---------------------------------------------------------------- launch
extern "C" void kernel_launch(void* const* d_in, const int* in_sizes, int n_in,
                              void* d_out, int out_size) {
    const float* hs    = (const float*)d_in[0];
    const float* embed = (const float*)d_in[1];
    const float* Wenc  = (const float*)d_in[2];
    const float* benc  = (const float*)d_in[3];
    const float* Wdec  = (const float*)d_in[4];
    const float* bdec  = (const float*)d_in[5];
    const float* Wih0  = (const float*)d_in[6];
    const float* Whh0  = (const float*)d_in[7];
    const float* bih0  = (const float*)d_in[8];
    const float* bhh0  = (const float*)d_in[9];
    const float* Wih1  = (const float*)d_in[10];
    const float* Whh1  = (const float*)d_in[11];
    const float* bih1  = (const float*)d_in[12];
    const float* bhh1  = (const float*)d_in[13];
    const float* Wout  = (const float*)d_in[14];
    const float* bout  = (const float*)d_in[15];
    const int*   hlens = (const int*)d_in[16];
    const void*  ys    = (const void*)d_in[17];

    __nv_bfloat16 *hsb, *preb, *eysb, *Wencb, *Woutb, *Wc0e, *zallb;
    float *yall, *bs0r, *emb0;
    cudaGetSymbolAddress((void**)&hsb,   g_hsb);
    cudaGetSymbolAddress((void**)&preb,  g_preb);
    cudaGetSymbolAddress((void**)&eysb,  g_eysb);
    cudaGetSymbolAddress((void**)&Wencb, g_Wencb);
    cudaGetSymbolAddress((void**)&Woutb, g_Woutb);
    cudaGetSymbolAddress((void**)&Wc0e,  g_Wc0e);
    cudaGetSymbolAddress((void**)&zallb, g_zallb);
    cudaGetSymbolAddress((void**)&yall,  g_yall);
    cudaGetSymbolAddress((void**)&bs0r,  g_bs0r);
    cudaGetSymbolAddress((void**)&emb0,  g_emb0);

    static int smem_set = 0;
    if (!smem_set) {
        cudaFuncSetAttribute(k_loop, cudaFuncAttributeMaxDynamicSharedMemorySize, SMSZ);
        cudaFuncSetAttribute(mma_big<0>, cudaFuncAttributeMaxDynamicSharedMemorySize, BIG_SMEM);
        cudaFuncSetAttribute(mma_big<1>, cudaFuncAttributeMaxDynamicSharedMemorySize, BIG_SMEM);
        smem_set = 1;
    }

    k_prep_all<<<296, 256>>>(hs, embed, Wenc, Wdec, Wout,
                             Wih0, Whh0, Wih1, Whh1,
                             bih0, bhh0, bih1, bhh1, ys);

    mma_big<0><<<dim3(4096 / 128, (L1 * BB + 127) / 128), 256, BIG_SMEM>>>(
        eysb, Wc0e, bs0r, emb0, nullptr, L1 * BB, 4096, 1024);

    mma_big<1><<<dim3(DD / 128, BB * TT / 128), 256, BIG_SMEM>>>(
        hsb, Wencb, benc, nullptr, preb, BB * TT, DD, DD);

    k_loop<<<NBLK, 256, SMSZ>>>(hlens, bdec);

    mma_big<0><<<dim3((VV + 127) / 128, (L1 * BB + 127) / 128), 256, BIG_SMEM>>>(
        zallb, Woutb, bout, yall, nullptr, L1 * BB, VV, 2048);

    k_ce<<<L1 * BB, 256>>>(ys);
    k_fin<<<1, 1>>>((float*)d_out);
}

// round 10
// speedup vs baseline: 1.0619x; 1.0619x over previous
#include <cuda_runtime.h>
#include <cuda_bf16.h>

#define BB 32
#define TT 400
#define DD 1024
#define VV 5000
#define LL 100
#define L1 101
#define NEGBIG -1e30f
#define NBLK 148
#define SMSZ 202752
#define BIG_SMEM 110592

__device__ __align__(16) __nv_bfloat16 g_hsb [BB * TT * DD];
__device__ __align__(16) __nv_bfloat16 g_preb[BB * TT * DD];
__device__ __align__(16) __nv_bfloat16 g_eysb[L1 * BB * DD];
__device__ __align__(16) __nv_bfloat16 g_Wencb[DD * DD];
__device__ __align__(16) __nv_bfloat16 g_Wdecb[DD * DD];
__device__ __align__(16) __nv_bfloat16 g_Woutb[VV * 2048];
__device__ __align__(16) __nv_bfloat16 g_Wc0e[4096 * 1024];
__device__ __align__(16) __nv_bfloat16 g_Wc0x[4096 * 2048];
__device__ __align__(16) __nv_bfloat16 g_Wc1r[4096 * 2048];
__device__ __align__(16) float g_bs0r[4096];
__device__ __align__(16) float g_bs1r[4096];
__device__ __align__(16) float g_emb0[(long long)L1 * BB * 4096];
__device__ __align__(16) __nv_bfloat16 g_dqb[BB * DD];
__device__ __align__(16) __nv_bfloat16 g_attb[BB * DD];
__device__ __align__(16) __nv_bfloat16 g_z0s[2][BB * DD];
__device__ __align__(16) __nv_bfloat16 g_z1s[2][BB * DD];
__device__ __align__(16) float g_c0[BB * DD];
__device__ __align__(16) float g_c1[BB * DD];
__device__ __align__(16) float g_pc[148 * 1024];
__device__ __align__(16) float g_ms[304];
__device__ unsigned g_cmb[32];
__device__ __align__(16) __nv_bfloat16 g_zallb[L1 * BB * 2048];
__device__ __align__(16) float g_yall[(long long)L1 * BB * VV];
__device__ float g_loss;
__device__ int g_i64;
// hierarchical barrier: 4 padded sub-counters (128B apart) + master + release
__device__ __align__(128) unsigned g_sub[4 * 32];
__device__ unsigned g_master;
__device__ unsigned g_release;

__device__ __forceinline__ float sigm(float x) { return 1.0f / (1.0f + expf(-x)); }
__device__ __forceinline__ int read_ys(const void* ys, int i) {
    return g_i64 ? (int)((const long long*)ys)[i] : ((const int*)ys)[i];
}
__device__ __forceinline__ unsigned sptr(const void* p) {
    unsigned r;
    asm("{.reg .u64 t; cvta.to.shared.u64 t, %1; cvt.u32.u64 %0, t;}" : "=r"(r) : "l"(p));
    return r;
}
__device__ __forceinline__ void cpa16(unsigned s, const void* g) {
    asm volatile("cp.async.cg.shared.global [%0], [%1], 16;" :: "r"(s), "l"(g));
}
#define CP_COMMIT asm volatile("cp.async.commit_group;")
#define CP_WAIT2  asm volatile("cp.async.wait_group 2;")
#define CP_WAIT1  asm volatile("cp.async.wait_group 1;")

__device__ __forceinline__ unsigned pack2(float a, float b) {
    __nv_bfloat162 p = __floats2bfloat162_rn(a, b);
    return *(unsigned*)&p;
}

// ---------------------------------------------------------------- fused prologue
__global__ void k_prep_all(
    const float* __restrict__ hs, const float* __restrict__ embed,
    const float* __restrict__ Wenc, const float* __restrict__ Wdec,
    const float* __restrict__ Wout,
    const float* __restrict__ Wih0, const float* __restrict__ Whh0,
    const float* __restrict__ Wih1, const float* __restrict__ Whh1,
    const float* __restrict__ bih0, const float* __restrict__ bhh0,
    const float* __restrict__ bih1, const float* __restrict__ bhh1,
    const void* __restrict__ ys)
{
    __shared__ int s_i64;
    const int tid = threadIdx.x;
    if (tid == 0) {
        const int* w = (const int*)ys;
        int f = 1;
        for (int j = 1; j < 64; j += 2) if (w[j] != 0) f = 0;
        s_i64 = f;
    }
    __syncthreads();
    const int i64 = s_i64;
    const long long gi = (long long)blockIdx.x * blockDim.x + tid;
    const long long gn = (long long)gridDim.x * blockDim.x;

    {
        __nv_bfloat16 z = __float2bfloat16(0.f);
        for (long long j = gi; j < BB * DD; j += gn) {
            g_c0[j] = 0.f; g_c1[j] = 0.f;
            g_z0s[0][j] = z; g_z0s[1][j] = z;
            g_z1s[0][j] = z; g_z1s[1][j] = z;
        }
        for (long long j = gi; j < 4096; j += gn) {
            int u = (int)j >> 2, gate = (int)j & 3;
            int orow = gate * 1024 + u;
            g_bs0r[j] = bih0[orow] + bhh0[orow];
            g_bs1r[j] = bih1[orow] + bhh1[orow];
        }
        if (gi < 32) g_cmb[gi] = 0u;
        if (gi < 128) g_sub[gi] = 0u;
        if (gi == 0) { g_loss = 0.f; g_master = 0u; g_release = 0u; g_i64 = i64; }
    }
    {
        const float4* s = (const float4*)hs;
        uint4* d = (uint4*)g_hsb;
        for (long long j = gi; j < 1638400LL; j += gn) {
            float4 a = s[2 * j], b = s[2 * j + 1];
            d[j] = make_uint4(pack2(a.x, a.y), pack2(a.z, a.w), pack2(b.x, b.y), pack2(b.z, b.w));
        }
    }
    {
        const float4* s = (const float4*)Wenc;
        uint4* d = (uint4*)g_Wencb;
        for (long long j = gi; j < 131072LL; j += gn) {
            float4 a = s[2 * j], b = s[2 * j + 1];
            d[j] = make_uint4(pack2(a.x, a.y), pack2(a.z, a.w), pack2(b.x, b.y), pack2(b.z, b.w));
        }
    }
    {
        const float4* s = (const float4*)Wdec;
        uint4* d = (uint4*)g_Wdecb;
        for (long long j = gi; j < 131072LL; j += gn) {
            float4 a = s[2 * j], b = s[2 * j + 1];
            d[j] = make_uint4(pack2(a.x, a.y), pack2(a.z, a.w), pack2(b.x, b.y), pack2(b.z, b.w));
        }
    }
    {
        const float4* s = (const float4*)Wout;
        uint4* d = (uint4*)g_Woutb;
        for (long long j = gi; j < 1280000LL; j += gn) {
            float4 a = s[2 * j], b = s[2 * j + 1];
            d[j] = make_uint4(pack2(a.x, a.y), pack2(a.z, a.w), pack2(b.x, b.y), pack2(b.z, b.w));
        }
    }
    {
        for (long long it = gi; it < 413696LL; it += gn) {
            int row = (int)(it >> 7), col = (int)(it & 127);
            int l = row >> 5, b = row & 31;
            int tok = 4999;
            if (l > 0) {
                int idx = b * LL + l - 1;
                tok = i64 ? (int)((const long long*)ys)[idx] : ((const int*)ys)[idx];
            }
            float4 v = ((const float4*)(embed + (long long)tok * 1024))[col];
            ((uint2*)(g_eysb + (long long)row * 1024))[col] = make_uint2(pack2(v.x, v.y), pack2(v.z, v.w));
        }
    }
    {
        for (long long j4 = gi; j4 < 1048576LL; j4 += gn) {
            long long j = j4 * 4;
            int r = (int)(j >> 10), c = (int)(j & 1023);
            long long orow = (r & 3) * 1024 + (r >> 2);
            float4 v = *(const float4*)(Wih0 + orow * 2048 + c);
            *(uint2*)(g_Wc0e + j) = make_uint2(pack2(v.x, v.y), pack2(v.z, v.w));
        }
    }
    {
        for (long long j4 = gi; j4 < 2097152LL; j4 += gn) {
            long long j = j4 * 4;
            int r = (int)(j >> 11), c = (int)(j & 2047);
            long long orow = (r & 3) * 1024 + (r >> 2);
            float4 v = (c < 1024) ? *(const float4*)(Wih0 + orow * 2048 + 1024 + c)
                                  : *(const float4*)(Whh0 + orow * 1024 + (c - 1024));
            *(uint2*)(g_Wc0x + j) = make_uint2(pack2(v.x, v.y), pack2(v.z, v.w));
        }
    }
    {
        for (long long j4 = gi; j4 < 2097152LL; j4 += gn) {
            long long j = j4 * 4;
            int r = (int)(j >> 11), c = (int)(j & 2047);
            long long orow = (r & 3) * 1024 + (r >> 2);
            float4 v = (c < 1024) ? *(const float4*)(Wih1 + orow * 1024 + c)
                                  : *(const float4*)(Whh1 + orow * 1024 + (c - 1024));
            *(uint2*)(g_Wc1r + j) = make_uint2(pack2(v.x, v.y), pack2(v.z, v.w));
        }
    }
}

__device__ __forceinline__ void mma_bf16(float* d, const unsigned* a, const unsigned* b) {
    asm volatile(
        "mma.sync.aligned.m16n8k16.row.col.f32.bf16.bf16.f32 "
        "{%0,%1,%2,%3}, {%4,%5,%6,%7}, {%8,%9}, {%0,%1,%2,%3};\n"
        : "+f"(d[0]), "+f"(d[1]), "+f"(d[2]), "+f"(d[3])
        : "r"(a[0]), "r"(a[1]), "r"(a[2]), "r"(a[3]), "r"(b[0]), "r"(b[1]));
}

// ---------------------------------------------------------------- big GEMM
#define BKP 72
__device__ __forceinline__ void issue_big(
    char* smb, int slot, int k0,
    const __nv_bfloat16* A, const __nv_bfloat16* B,
    int M, int N, int K, int m0, int n0)
{
    __nv_bfloat16* smA = (__nv_bfloat16*)smb + slot * (2 * 128 * BKP);
    __nv_bfloat16* smB = smA + 128 * BKP;
    const int tid = threadIdx.x;
#pragma unroll
    for (int j = 0; j < 4; j++) {
        int idx = tid + j * 256;
        int r = idx >> 3, c = (idx & 7) * 8;
        int m = m0 + r; if (m >= M) m = 0;
        cpa16(sptr(smA + r * BKP + c), A + (long long)m * K + k0 + c);
        int n = n0 + r; if (n >= N) n = 0;
        cpa16(sptr(smB + r * BKP + c), B + (long long)n * K + k0 + c);
    }
}

template <int EPI>
__global__ __launch_bounds__(256) void mma_big(
    const __nv_bfloat16* __restrict__ A, const __nv_bfloat16* __restrict__ B,
    const float* __restrict__ bias, float* __restrict__ Cf,
    __nv_bfloat16* __restrict__ Cb, int M, int N, int K)
{
    extern __shared__ char smb[];
    const int tid = threadIdx.x, lane = tid & 31, wid = tid >> 5;
    const int wm = wid >> 1, wn = wid & 1;
    const int m0 = blockIdx.y * 128, n0 = blockIdx.x * 128;
    const int g = lane >> 2, tg = lane & 3;
    const int S = K >> 6;

    float acc[2][8][4];
#pragma unroll
    for (int a = 0; a < 2; a++)
#pragma unroll
        for (int b = 0; b < 8; b++)
#pragma unroll
            for (int c = 0; c < 4; c++) acc[a][b][c] = 0.f;

    issue_big(smb, 0, 0, A, B, M, N, K, m0, n0); CP_COMMIT;
    if (S > 1) issue_big(smb, 1, 64, A, B, M, N, K, m0, n0);
    CP_COMMIT;

    for (int si = 0; si < S; si++) {
        CP_WAIT1;
        __syncthreads();
        if (si + 2 < S) issue_big(smb, (si + 2) % 3, (si + 2) << 6, A, B, M, N, K, m0, n0);
        CP_COMMIT;
        __nv_bfloat16 (*As)[BKP] = (__nv_bfloat16(*)[BKP])((__nv_bfloat16*)smb + (si % 3) * (2 * 128 * BKP));
        __nv_bfloat16 (*Bs)[BKP] = (__nv_bfloat16(*)[BKP])((__nv_bfloat16*)smb + (si % 3) * (2 * 128 * BKP) + 128 * BKP);
#pragma unroll
        for (int kt = 0; kt < 4; kt++) {
            const int c0 = kt * 16 + tg * 2;
            unsigned af[2][4];
#pragma unroll
            for (int mt = 0; mt < 2; mt++) {
                int r = wm * 32 + mt * 16 + g;
                af[mt][0] = *(const unsigned*)&As[r][c0];
                af[mt][1] = *(const unsigned*)&As[r + 8][c0];
                af[mt][2] = *(const unsigned*)&As[r][c0 + 8];
                af[mt][3] = *(const unsigned*)&As[r + 8][c0 + 8];
            }
#pragma unroll
            for (int nt = 0; nt < 8; nt++) {
                int n = wn * 64 + nt * 8 + g;
                unsigned bf[2];
                bf[0] = *(const unsigned*)&Bs[n][c0];
                bf[1] = *(const unsigned*)&Bs[n][c0 + 8];
                mma_bf16(acc[0][nt], af[0], bf);
                mma_bf16(acc[1][nt], af[1], bf);
            }
        }
    }

#pragma unroll
    for (int mt = 0; mt < 2; mt++) {
#pragma unroll
        for (int nt = 0; nt < 8; nt++) {
            int r = m0 + wm * 32 + mt * 16 + g;
            int c = n0 + wn * 64 + nt * 8 + tg * 2;
            float* a = acc[mt][nt];
            if (EPI == 0) {
                float b0 = (c < N) ? bias[c] : 0.f;
                float b1 = (c + 1 < N) ? bias[c + 1] : 0.f;
                if (r < M) {
                    if (c < N)     Cf[(long long)r * N + c]     = a[0] + b0;
                    if (c + 1 < N) Cf[(long long)r * N + c + 1] = a[1] + b1;
                }
                if (r + 8 < M) {
                    if (c < N)     Cf[(long long)(r + 8) * N + c]     = a[2] + b0;
                    if (c + 1 < N) Cf[(long long)(r + 8) * N + c + 1] = a[3] + b1;
                }
            } else {
                float b0 = bias[c], b1 = bias[c + 1];
                __nv_bfloat162 v0 = __floats2bfloat162_rn(tanhf(a[0] + b0), tanhf(a[1] + b1));
                __nv_bfloat162 v1 = __floats2bfloat162_rn(tanhf(a[2] + b0), tanhf(a[3] + b1));
                *(__nv_bfloat162*)(Cb + (long long)r * N + c) = v0;
                *(__nv_bfloat162*)(Cb + (long long)(r + 8) * N + c) = v1;
            }
        }
    }
}

// ---------------------------------------------------------------- hierarchical barrier
// 4 sub-counters in distinct 128B lines (37 blocks each), 1 master, 1 release word.
__device__ __forceinline__ void gbar(int e) {
    __syncthreads();
    if (threadIdx.x == 0) {
        __threadfence();
        const int grp = blockIdx.x & 3;
        unsigned old = atomicAdd(&g_sub[grp << 5], 1u);
        bool released = false;
        if (old == (unsigned)e * 37u + 36u) {
            unsigned m = atomicAdd(&g_master, 1u);
            if (m == (unsigned)e * 4u + 3u) {
                atomicExch(&g_release, (unsigned)(e + 1));
                released = true;
            }
        }
        if (!released) {
            unsigned r;
            do { asm volatile("ld.global.cg.u32 %0, [%1];" : "=r"(r) : "l"(&g_release)); }
            while (r < (unsigned)(e + 1));
        }
        __threadfence();
    }
    __syncthreads();
}

// ---------------------------------------------------------------- tile GEMM
// K-chunk = 256, 4 slots (3 in flight). AKIND: 0=A0[32][1024]; 2=[A0|A1].
// EPI: 0=tanh->outb; 1=LSTM pointwise (NT=4). HASEB: per-row fp32 bias (g0).
template <int AKIND, int NT>
__device__ __forceinline__ void issue_chunk(
    char* smraw, int slot, int kc, int K,
    const __nv_bfloat16* A0, const __nv_bfloat16* A1,
    const __nv_bfloat16* B, int n0)
{
    constexpr int ASZ = 32 * 264;
    constexpr int STE = ASZ + NT * 8 * 264;
    __nv_bfloat16* smA = (__nv_bfloat16*)smraw + slot * STE;
    __nv_bfloat16* smB = smA + ASZ;
    const int tid = threadIdx.x;
    const int kbase = kc << 8;
    const int region = kbase >> 10;
    const int koff = kbase & 1023;
#pragma unroll
    for (int j = 0; j < 4; j++) {
        int u = tid + j * 256;
        int r = u >> 5, c = (u & 31) << 3;
        const __nv_bfloat16* src;
        if (AKIND == 0) src = A0 + r * 1024 + kbase + c;
        else src = (region == 0 ? A0 : A1) + r * 1024 + koff + c;
        cpa16(sptr(smA + r * 264 + c), src);
    }
#pragma unroll
    for (int j = 0; j < NT; j++) {
        int u = tid + j * 256;
        int r = u >> 5, c = (u & 31) << 3;
        cpa16(sptr(smB + r * 264 + c), B + (long long)(n0 + r) * K + kbase + c);
    }
}

template <int AKIND, int EPI, int NT, bool ZALL, bool HASEB>
__device__ void gtile(char* smraw, int n0, int K,
                      const __nv_bfloat16* __restrict__ B, const float* __restrict__ bias,
                      const __nv_bfloat16* A0, const __nv_bfloat16* A1,
                      __nv_bfloat16* outb, float* cst, __nv_bfloat16* znew,
                      __nv_bfloat16* zallp, int step, const float* eb)
{
    constexpr int ASZ = 32 * 264;
    constexpr int STE = ASZ + NT * 8 * 264;
    constexpr int NW = 32 * NT * 8;
    const int tid = threadIdx.x, lane = tid & 31, wid = tid >> 5;
    const int g = lane >> 2, tg = lane & 3;
    const int S = K >> 8;

    float acc[2][NT][4];
#pragma unroll
    for (int a = 0; a < 2; a++)
#pragma unroll
        for (int b = 0; b < NT; b++)
#pragma unroll
            for (int c = 0; c < 4; c++) acc[a][b][c] = 0.f;

#pragma unroll
    for (int st = 0; st < 3; st++) {
        if (st < S) issue_chunk<AKIND, NT>(smraw, st, st, K, A0, A1, B, n0);
        CP_COMMIT;
    }

    for (int si = 0; si < S; si++) {
        CP_WAIT2;
        __syncthreads();
        int nx = si + 3;
        if (nx < S) issue_chunk<AKIND, NT>(smraw, nx & 3, nx, K, A0, A1, B, n0);
        CP_COMMIT;
        __nv_bfloat16 (*As)[264] = (__nv_bfloat16(*)[264])((__nv_bfloat16*)smraw + (si & 3) * STE);
        __nv_bfloat16 (*Bs)[264] = (__nv_bfloat16(*)[264])((__nv_bfloat16*)smraw + (si & 3) * STE + ASZ);
#pragma unroll
        for (int ks = 0; ks < 2; ks++) {
            const int c0 = wid * 32 + ks * 16 + tg * 2;
            unsigned af[2][4];
#pragma unroll
            for (int mt = 0; mt < 2; mt++) {
                int r = mt * 16 + g;
                af[mt][0] = *(const unsigned*)&As[r][c0];
                af[mt][1] = *(const unsigned*)&As[r + 8][c0];
                af[mt][2] = *(const unsigned*)&As[r][c0 + 8];
                af[mt][3] = *(const unsigned*)&As[r + 8][c0 + 8];
            }
#pragma unroll
            for (int nt = 0; nt < NT; nt++) {
                int n = nt * 8 + g;
                unsigned bf[2];
                bf[0] = *(const unsigned*)&Bs[n][c0];
                bf[1] = *(const unsigned*)&Bs[n][c0 + 8];
                mma_bf16(acc[0][nt], af[0], bf);
                mma_bf16(acc[1][nt], af[1], bf);
            }
        }
    }
    __syncthreads();

    float* Pred = (float*)smraw;
    {
        int base = wid * NW;
#pragma unroll
        for (int mt = 0; mt < 2; mt++)
#pragma unroll
            for (int nt = 0; nt < NT; nt++) {
                int r = mt * 16 + g, cl = nt * 8 + tg * 2;
                Pred[base + r * (NT * 8) + cl]           = acc[mt][nt][0];
                Pred[base + r * (NT * 8) + cl + 1]       = acc[mt][nt][1];
                Pred[base + (r + 8) * (NT * 8) + cl]     = acc[mt][nt][2];
                Pred[base + (r + 8) * (NT * 8) + cl + 1] = acc[mt][nt][3];
            }
    }
    __syncthreads();

    if (EPI == 0) {
        for (int o = tid; o < NW; o += 256) {
            int r = o / (NT * 8), c = o % (NT * 8);
            float sum = 0.f;
#pragma unroll
            for (int w = 0; w < 8; w++) sum += Pred[w * NW + o];
            outb[r * 1024 + n0 + c] = __float2bfloat16(tanhf(sum + bias[n0 + c]));
        }
    } else {
        int b = tid >> 3, ul = tid & 7;
        float gv[4];
#pragma unroll
        for (int gate = 0; gate < 4; gate++) {
            int col = ul * 4 + gate;
            float sum = 0.f;
#pragma unroll
            for (int w = 0; w < 8; w++) sum += Pred[w * 1024 + b * 32 + col];
            float bb = HASEB ? eb[b * 4096 + n0 + col] : bias[n0 + col];
            gv[gate] = sum + bb;
        }
        int u = (n0 >> 2) + ul;
        int gid = b * 1024 + u;
        float cv = sigm(gv[1]) * cst[gid] + sigm(gv[0]) * tanhf(gv[2]);
        float h = sigm(gv[3]) * tanhf(cv);
        cst[gid] = cv;
        znew[gid] = __float2bfloat16(h);
        if (ZALL) zallp[(long long)(step * 32 + b) * 2048 + u] = __float2bfloat16(h);
    }
    __syncthreads();
}

// ---------------------------------------------------------------- attention
// 148 blocks: b<20 -> 5 chunks of 80 t; b>=20 -> 4 chunks of 100 t.
__device__ void phase_epc(char* smraw, int s, const int* __restrict__ hlens) {
    const int bid = blockIdx.x;
    int b, t0, tlen, ncs, base;
    if (bid < 100) { b = bid / 5; t0 = (bid % 5) * 80; tlen = 80; ncs = 5; base = b * 5; }
    else { int u = bid - 100; b = 20 + (u >> 2); t0 = (u & 3) * 100; tlen = 100; ncs = 4; base = 100 + (b - 20) * 4; }

    const int tid = threadIdx.x, lane = tid & 31, wid = tid >> 5;
    float* dqs = (float*)smraw;
    float* ws  = dqs + 1024;
    float* red = ws + 104;
    float* pcr = red + 256;
    int*   flg = (int*)(pcr + 8192);

    const uint4* dqp = (const uint4*)(g_dqb + b * 1024);
    for (int j = tid; j < 128; j += 256) {
        uint4 v = __ldcg(dqp + j);
        const __nv_bfloat162* h = (const __nv_bfloat162*)&v;
#pragma unroll
        for (int k = 0; k < 4; k++) {
            float2 f = __bfloat1622float2(h[k]);
            dqs[j * 8 + k * 2]     = f.x;
            dqs[j * 8 + k * 2 + 1] = f.y;
        }
    }
    __syncthreads();

    const int hl = hlens[b];
    for (int bs = wid * 2; bs < tlen; bs += 16) {
        const __nv_bfloat16* r1 = g_preb + ((long long)b * 400 + t0 + bs) * 1024 + lane * 8;
        const __nv_bfloat16* r2 = r1 + 1024;
        float a1 = 0.f, a2 = 0.f, a3 = 0.f, a4 = 0.f;
#pragma unroll
        for (int q = 0; q < 4; q++) {
            uint4 v1 = *(const uint4*)(r1 + q * 256);
            uint4 v2 = *(const uint4*)(r2 + q * 256);
            const __nv_bfloat162* h1 = (const __nv_bfloat162*)&v1;
            const __nv_bfloat162* h2 = (const __nv_bfloat162*)&v2;
#pragma unroll
            for (int k = 0; k < 4; k++) {
                float2 d = *(const float2*)(dqs + q * 256 + lane * 8 + k * 2);
                float2 f1 = __bfloat1622float2(h1[k]);
                float2 f2 = __bfloat1622float2(h2[k]);
                a1 = fmaf(f1.x, d.x, a1); a2 = fmaf(f1.y, d.y, a2);
                a3 = fmaf(f2.x, d.x, a3); a4 = fmaf(f2.y, d.y, a4);
            }
        }
        float s1 = a1 + a2, s2 = a3 + a4;
#pragma unroll
        for (int off = 16; off; off >>= 1) {
            s1 += __shfl_xor_sync(0xffffffffu, s1, off);
            s2 += __shfl_xor_sync(0xffffffffu, s2, off);
        }
        if (lane == 0) {
            int t = t0 + bs;
            ws[bs]     = (t < hl)     ? 2.f * s1 : NEGBIG;
            ws[bs + 1] = (t + 1 < hl) ? 2.f * s2 : NEGBIG;
        }
    }
    __syncthreads();

    float lm = NEGBIG;
    for (int i = tid; i < tlen; i += 256) lm = fmaxf(lm, ws[i]);
    red[tid] = lm; __syncthreads();
    for (int st = 128; st; st >>= 1) { if (tid < st) red[tid] = fmaxf(red[tid], red[tid + st]); __syncthreads(); }
    const float m = red[0]; __syncthreads();
    float ls = 0.f;
    for (int i = tid; i < tlen; i += 256) { float w = expf(ws[i] - m); ws[i] = w; ls += w; }
    red[tid] = ls; __syncthreads();
    for (int st = 128; st; st >>= 1) { if (tid < st) red[tid] += red[tid + st]; __syncthreads(); }
    const float sl = red[0];
    __syncthreads();

    float pacc[32];
#pragma unroll
    for (int i = 0; i < 32; i++) pacc[i] = 0.f;
    for (int bs = wid * 2; bs < tlen; bs += 16) {
        float w1 = ws[bs], w2 = ws[bs + 1];
        const __nv_bfloat16* r1 = g_hsb + ((long long)b * 400 + t0 + bs) * 1024 + lane * 8;
        const __nv_bfloat16* r2 = r1 + 1024;
#pragma unroll
        for (int q = 0; q < 4; q++) {
            uint4 v1 = *(const uint4*)(r1 + q * 256);
            uint4 v2 = *(const uint4*)(r2 + q * 256);
            const __nv_bfloat162* h1 = (const __nv_bfloat162*)&v1;
            const __nv_bfloat162* h2 = (const __nv_bfloat162*)&v2;
#pragma unroll
            for (int k = 0; k < 4; k++) {
                float2 f1 = __bfloat1622float2(h1[k]);
                float2 f2 = __bfloat1622float2(h2[k]);
                int o = q * 8 + k * 2;
                pacc[o]     = fmaf(w1, f1.x, fmaf(w2, f2.x, pacc[o]));
                pacc[o + 1] = fmaf(w1, f1.y, fmaf(w2, f2.y, pacc[o + 1]));
            }
        }
    }
#pragma unroll
    for (int q = 0; q < 4; q++)
#pragma unroll
        for (int j = 0; j < 8; j++)
            pcr[wid * 1024 + q * 256 + lane * 8 + j] = pacc[q * 8 + j];
    __syncthreads();
    for (int col = tid; col < 1024; col += 256) {
        float a = 0.f;
#pragma unroll
        for (int w = 0; w < 8; w++) a += pcr[w * 1024 + col];
        g_pc[bid * 1024 + col] = a;
    }
    if (tid == 0) { g_ms[bid * 2] = m; g_ms[bid * 2 + 1] = sl; }
    __syncthreads();

    if (tid == 0) {
        __threadfence();
        unsigned old = atomicAdd(&g_cmb[b], 1u);
        *flg = (old == (unsigned)(s * ncs + ncs - 1)) ? 1 : 0;
    }
    __syncthreads();
    if (*flg) {
        float mi[5], si[5];
        for (int i = 0; i < ncs; i++) {
            mi[i] = __ldcg(&g_ms[(base + i) * 2]);
            si[i] = __ldcg(&g_ms[(base + i) * 2 + 1]);
        }
        float M = NEGBIG;
        for (int i = 0; i < ncs; i++) M = fmaxf(M, mi[i]);
        float sc[5], Ssum = 0.f;
        for (int i = 0; i < ncs; i++) { sc[i] = expf(mi[i] - M); Ssum += sc[i] * si[i]; }
        float inv = 1.f / Ssum;
        for (int col = tid; col < 1024; col += 256) {
            float a = 0.f;
            for (int i = 0; i < ncs; i++) a += sc[i] * __ldcg(&g_pc[(base + i) * 1024 + col]);
            __nv_bfloat16 v = __float2bfloat16(a * inv);
            g_attb[b * 1024 + col] = v;
            g_zallb[((long long)s * 32 + b) * 2048 + 1024 + col] = v;
        }
    }
    __syncthreads();
}

// ---------------------------------------------------------------- main loop (round-8 schedule)
__global__ void __launch_bounds__(256, 1) k_loop(const int* __restrict__ hlens,
                                                 const float* __restrict__ bdec) {
    extern __shared__ char sm[];
    const int bid = blockIdx.x;
    int ep = 0;

    for (int s = 0; s <= 101; s++) {
        const int p = s & 1;
        if (bid < 128) {
            if (s >= 1)
                gtile<2, 1, 4, true, false>(sm, bid * 32, 2048, g_Wc1r, g_bs1r,
                                            g_z0s[p], g_z1s[1 - p],
                                            nullptr, g_c1, g_z1s[p], g_zallb, s - 1, nullptr);
        } else if (bid < 144) {
            if (s <= 100)
                gtile<0, 0, 8, false, false>(sm, (bid - 128) * 64, 1024, g_Wdecb, bdec,
                                             g_z0s[p], nullptr,
                                             g_dqb, nullptr, nullptr, nullptr, s, nullptr);
        }
        gbar(ep); ep++;
        if (s == 101) break;

        phase_epc(sm, s, hlens);
        gbar(ep); ep++;

        if (bid < 128) {
            gtile<2, 1, 4, false, true>(sm, bid * 32, 2048, g_Wc0x, nullptr,
                                        g_attb, g_z0s[p],
                                        nullptr, g_c0, g_z0s[1 - p], nullptr, s,
                                        g_emb0 + (long long)s * 32 * 4096);
        }
        gbar(ep); ep++;
    }
}

// ---------------------------------------------------------------- CE
__global__ void k_ce(const void* __restrict__ ys) {
    int r = blockIdx.x;
    int l = r / BB, b = r % BB;
    const float* y = g_yall + (long long)r * VV;
    __shared__ float red[256];
    int tid = threadIdx.x;
    float lm = NEGBIG;
    for (int v = tid; v < VV; v += 256) lm = fmaxf(lm, y[v]);
    red[tid] = lm; __syncthreads();
    for (int s = 128; s > 0; s >>= 1) { if (tid < s) red[tid] = fmaxf(red[tid], red[tid + s]); __syncthreads(); }
    float m = red[0]; __syncthreads();
    float ls = 0.f;
    for (int v = tid; v < VV; v += 256) ls += expf(y[v] - m);
    red[tid] = ls; __syncthreads();
    for (int s = 128; s > 0; s >>= 1) { if (tid < s) red[tid] += red[tid + s]; __syncthreads(); }
    if (tid == 0) {
        int tgt = (l < LL) ? read_ys(ys, b * LL + l) : 4999;
        atomicAdd(&g_loss, logf(red[0]) + m - y[tgt]);
    }
}

__global__ void k_fin(float* out) {
    out[0] = g_loss * ((float)LL / (float)(L1 * BB));
}

// ---------------------------------------------------------------- launch
extern "C" void kernel_launch(void* const* d_in, const int* in_sizes, int n_in,
                              void* d_out, int out_size) {
    const float* hs    = (const float*)d_in[0];
    const float* embed = (const float*)d_in[1];
    const float* Wenc  = (const float*)d_in[2];
    const float* benc  = (const float*)d_in[3];
    const float* Wdec  = (const float*)d_in[4];
    const float* bdec  = (const float*)d_in[5];
    const float* Wih0  = (const float*)d_in[6];
    const float* Whh0  = (const float*)d_in[7];
    const float* bih0  = (const float*)d_in[8];
    const float* bhh0  = (const float*)d_in[9];
    const float* Wih1  = (const float*)d_in[10];
    const float* Whh1  = (const float*)d_in[11];
    const float* bih1  = (const float*)d_in[12];
    const float* bhh1  = (const float*)d_in[13];
    const float* Wout  = (const float*)d_in[14];
    const float* bout  = (const float*)d_in[15];
    const int*   hlens = (const int*)d_in[16];
    const void*  ys    = (const void*)d_in[17];

    __nv_bfloat16 *hsb, *preb, *eysb, *Wencb, *Woutb, *Wc0e, *zallb;
    float *yall, *bs0r, *emb0;
    cudaGetSymbolAddress((void**)&hsb,   g_hsb);
    cudaGetSymbolAddress((void**)&preb,  g_preb);
    cudaGetSymbolAddress((void**)&eysb,  g_eysb);
    cudaGetSymbolAddress((void**)&Wencb, g_Wencb);
    cudaGetSymbolAddress((void**)&Woutb, g_Woutb);
    cudaGetSymbolAddress((void**)&Wc0e,  g_Wc0e);
    cudaGetSymbolAddress((void**)&zallb, g_zallb);
    cudaGetSymbolAddress((void**)&yall,  g_yall);
    cudaGetSymbolAddress((void**)&bs0r,  g_bs0r);
    cudaGetSymbolAddress((void**)&emb0,  g_emb0);

    static int smem_set = 0;
    if (!smem_set) {
        cudaFuncSetAttribute(k_loop, cudaFuncAttributeMaxDynamicSharedMemorySize, SMSZ);
        cudaFuncSetAttribute(mma_big<0>, cudaFuncAttributeMaxDynamicSharedMemorySize, BIG_SMEM);
        cudaFuncSetAttribute(mma_big<1>, cudaFuncAttributeMaxDynamicSharedMemorySize, BIG_SMEM);
        smem_set = 1;
    }

    k_prep_all<<<296, 256>>>(hs, embed, Wenc, Wdec, Wout,
                             Wih0, Whh0, Wih1, Whh1,
                             bih0, bhh0, bih1, bhh1, ys);

    mma_big<0><<<dim3(4096 / 128, (L1 * BB + 127) / 128), 256, BIG_SMEM>>>(
        eysb, Wc0e, bs0r, emb0, nullptr, L1 * BB, 4096, 1024);

    mma_big<1><<<dim3(DD / 128, BB * TT / 128), 256, BIG_SMEM>>>(
        hsb, Wencb, benc, nullptr, preb, BB * TT, DD, DD);

    k_loop<<<NBLK, 256, SMSZ>>>(hlens, bdec);

    mma_big<0><<<dim3((VV + 127) / 128, (L1 * BB + 127) / 128), 256, BIG_SMEM>>>(
        zallb, Woutb, bout, yall, nullptr, L1 * BB, VV, 2048);

    k_ce<<<L1 * BB, 256>>>(ys);
    k_fin<<<1, 1>>>((float*)d_out);
}

// round 11
// speedup vs baseline: 1.1553x; 1.0880x over previous
#include <cuda_runtime.h>
#include <cuda_bf16.h>

#define BB 32
#define TT 400
#define DD 1024
#define VV 5000
#define LL 100
#define L1 101
#define NEGBIG -1e30f
#define NBLK 148
#define SMSZ 202752
#define BIG_SMEM 110592

__device__ __align__(16) __nv_bfloat16 g_hsb [BB * TT * DD];
__device__ __align__(16) __nv_bfloat16 g_preb[BB * TT * DD];
__device__ __align__(16) __nv_bfloat16 g_eysb[L1 * BB * DD];
__device__ __align__(16) __nv_bfloat16 g_Wencb[DD * DD];
__device__ __align__(16) __nv_bfloat16 g_Wdecb[DD * DD];
__device__ __align__(16) __nv_bfloat16 g_Woutb[VV * 2048];
__device__ __align__(16) __nv_bfloat16 g_Wc0e[4096 * 1024];
__device__ __align__(16) __nv_bfloat16 g_Wc0x[4096 * 2048];
__device__ __align__(16) __nv_bfloat16 g_Wc1r[4096 * 2048];
__device__ __align__(16) float g_bs0r[4096];
__device__ __align__(16) float g_bs1r[4096];
__device__ __align__(16) float g_emb0[(long long)L1 * BB * 4096];
__device__ __align__(16) __nv_bfloat16 g_dqb[BB * DD];
__device__ __align__(16) __nv_bfloat16 g_attb[BB * DD];
__device__ __align__(16) __nv_bfloat16 g_z0s[2][BB * DD];
__device__ __align__(16) __nv_bfloat16 g_z1s[2][BB * DD];
__device__ __align__(16) float g_c0[BB * DD];
__device__ __align__(16) float g_c1[BB * DD];
__device__ __align__(16) float g_pc[148 * 1024];
__device__ __align__(16) float g_ms[304];
__device__ unsigned g_cmb[32];
__device__ __align__(16) __nv_bfloat16 g_zallb[L1 * BB * 2048];
__device__ __align__(16) float g_yall[(long long)L1 * BB * VV];
__device__ float g_loss;
__device__ int g_i64;
__device__ unsigned g_arrive;
__device__ unsigned g_release;
__device__ unsigned g_dqf;

__device__ __forceinline__ float sigm(float x) { return 1.0f / (1.0f + expf(-x)); }
__device__ __forceinline__ int read_ys(const void* ys, int i) {
    return g_i64 ? (int)((const long long*)ys)[i] : ((const int*)ys)[i];
}
__device__ __forceinline__ unsigned sptr(const void* p) {
    unsigned r;
    asm("{.reg .u64 t; cvta.to.shared.u64 t, %1; cvt.u32.u64 %0, t;}" : "=r"(r) : "l"(p));
    return r;
}
__device__ __forceinline__ void cpa16(unsigned s, const void* g) {
    asm volatile("cp.async.cg.shared.global [%0], [%1], 16;" :: "r"(s), "l"(g));
}
#define CP_COMMIT asm volatile("cp.async.commit_group;")
#define CP_WAIT2  asm volatile("cp.async.wait_group 2;")
#define CP_WAIT1  asm volatile("cp.async.wait_group 1;")

__device__ __forceinline__ unsigned pack2(float a, float b) {
    __nv_bfloat162 p = __floats2bfloat162_rn(a, b);
    return *(unsigned*)&p;
}

// ---------------------------------------------------------------- fused prologue
__global__ void k_prep_all(
    const float* __restrict__ hs, const float* __restrict__ embed,
    const float* __restrict__ Wenc, const float* __restrict__ Wdec,
    const float* __restrict__ Wout,
    const float* __restrict__ Wih0, const float* __restrict__ Whh0,
    const float* __restrict__ Wih1, const float* __restrict__ Whh1,
    const float* __restrict__ bih0, const float* __restrict__ bhh0,
    const float* __restrict__ bih1, const float* __restrict__ bhh1,
    const void* __restrict__ ys)
{
    __shared__ int s_i64;
    const int tid = threadIdx.x;
    if (tid == 0) {
        const int* w = (const int*)ys;
        int f = 1;
        for (int j = 1; j < 64; j += 2) if (w[j] != 0) f = 0;
        s_i64 = f;
    }
    __syncthreads();
    const int i64 = s_i64;
    const long long gi = (long long)blockIdx.x * blockDim.x + tid;
    const long long gn = (long long)gridDim.x * blockDim.x;

    {
        __nv_bfloat16 z = __float2bfloat16(0.f);
        for (long long j = gi; j < BB * DD; j += gn) {
            g_c0[j] = 0.f; g_c1[j] = 0.f;
            g_z0s[0][j] = z; g_z0s[1][j] = z;
            g_z1s[0][j] = z; g_z1s[1][j] = z;
        }
        for (long long j = gi; j < 4096; j += gn) {
            int u = (int)j >> 2, gate = (int)j & 3;
            int orow = gate * 1024 + u;
            g_bs0r[j] = bih0[orow] + bhh0[orow];
            g_bs1r[j] = bih1[orow] + bhh1[orow];
        }
        if (gi < 32) g_cmb[gi] = 0u;
        if (gi == 0) { g_loss = 0.f; g_arrive = 0u; g_release = 0u; g_dqf = 0u; g_i64 = i64; }
    }
    {
        const float4* s = (const float4*)hs;
        uint4* d = (uint4*)g_hsb;
        for (long long j = gi; j < 1638400LL; j += gn) {
            float4 a = s[2 * j], b = s[2 * j + 1];
            d[j] = make_uint4(pack2(a.x, a.y), pack2(a.z, a.w), pack2(b.x, b.y), pack2(b.z, b.w));
        }
    }
    {
        const float4* s = (const float4*)Wenc;
        uint4* d = (uint4*)g_Wencb;
        for (long long j = gi; j < 131072LL; j += gn) {
            float4 a = s[2 * j], b = s[2 * j + 1];
            d[j] = make_uint4(pack2(a.x, a.y), pack2(a.z, a.w), pack2(b.x, b.y), pack2(b.z, b.w));
        }
    }
    {
        const float4* s = (const float4*)Wdec;
        uint4* d = (uint4*)g_Wdecb;
        for (long long j = gi; j < 131072LL; j += gn) {
            float4 a = s[2 * j], b = s[2 * j + 1];
            d[j] = make_uint4(pack2(a.x, a.y), pack2(a.z, a.w), pack2(b.x, b.y), pack2(b.z, b.w));
        }
    }
    {
        const float4* s = (const float4*)Wout;
        uint4* d = (uint4*)g_Woutb;
        for (long long j = gi; j < 1280000LL; j += gn) {
            float4 a = s[2 * j], b = s[2 * j + 1];
            d[j] = make_uint4(pack2(a.x, a.y), pack2(a.z, a.w), pack2(b.x, b.y), pack2(b.z, b.w));
        }
    }
    {
        for (long long it = gi; it < 413696LL; it += gn) {
            int row = (int)(it >> 7), col = (int)(it & 127);
            int l = row >> 5, b = row & 31;
            int tok = 4999;
            if (l > 0) {
                int idx = b * LL + l - 1;
                tok = i64 ? (int)((const long long*)ys)[idx] : ((const int*)ys)[idx];
            }
            float4 v = ((const float4*)(embed + (long long)tok * 1024))[col];
            ((uint2*)(g_eysb + (long long)row * 1024))[col] = make_uint2(pack2(v.x, v.y), pack2(v.z, v.w));
        }
    }
    {
        for (long long j4 = gi; j4 < 1048576LL; j4 += gn) {
            long long j = j4 * 4;
            int r = (int)(j >> 10), c = (int)(j & 1023);
            long long orow = (r & 3) * 1024 + (r >> 2);
            float4 v = *(const float4*)(Wih0 + orow * 2048 + c);
            *(uint2*)(g_Wc0e + j) = make_uint2(pack2(v.x, v.y), pack2(v.z, v.w));
        }
    }
    {
        for (long long j4 = gi; j4 < 2097152LL; j4 += gn) {
            long long j = j4 * 4;
            int r = (int)(j >> 11), c = (int)(j & 2047);
            long long orow = (r & 3) * 1024 + (r >> 2);
            float4 v = (c < 1024) ? *(const float4*)(Wih0 + orow * 2048 + 1024 + c)
                                  : *(const float4*)(Whh0 + orow * 1024 + (c - 1024));
            *(uint2*)(g_Wc0x + j) = make_uint2(pack2(v.x, v.y), pack2(v.z, v.w));
        }
    }
    {
        for (long long j4 = gi; j4 < 2097152LL; j4 += gn) {
            long long j = j4 * 4;
            int r = (int)(j >> 11), c = (int)(j & 2047);
            long long orow = (r & 3) * 1024 + (r >> 2);
            float4 v = (c < 1024) ? *(const float4*)(Wih1 + orow * 1024 + c)
                                  : *(const float4*)(Whh1 + orow * 1024 + (c - 1024));
            *(uint2*)(g_Wc1r + j) = make_uint2(pack2(v.x, v.y), pack2(v.z, v.w));
        }
    }
}

__device__ __forceinline__ void mma_bf16(float* d, const unsigned* a, const unsigned* b) {
    asm volatile(
        "mma.sync.aligned.m16n8k16.row.col.f32.bf16.bf16.f32 "
        "{%0,%1,%2,%3}, {%4,%5,%6,%7}, {%8,%9}, {%0,%1,%2,%3};\n"
        : "+f"(d[0]), "+f"(d[1]), "+f"(d[2]), "+f"(d[3])
        : "r"(a[0]), "r"(a[1]), "r"(a[2]), "r"(a[3]), "r"(b[0]), "r"(b[1]));
}

// ---------------------------------------------------------------- big GEMM
#define BKP 72
__device__ __forceinline__ void issue_big(
    char* smb, int slot, int k0,
    const __nv_bfloat16* A, const __nv_bfloat16* B,
    int M, int N, int K, int m0, int n0)
{
    __nv_bfloat16* smA = (__nv_bfloat16*)smb + slot * (2 * 128 * BKP);
    __nv_bfloat16* smB = smA + 128 * BKP;
    const int tid = threadIdx.x;
#pragma unroll
    for (int j = 0; j < 4; j++) {
        int idx = tid + j * 256;
        int r = idx >> 3, c = (idx & 7) * 8;
        int m = m0 + r; if (m >= M) m = 0;
        cpa16(sptr(smA + r * BKP + c), A + (long long)m * K + k0 + c);
        int n = n0 + r; if (n >= N) n = 0;
        cpa16(sptr(smB + r * BKP + c), B + (long long)n * K + k0 + c);
    }
}

template <int EPI>
__global__ __launch_bounds__(256) void mma_big(
    const __nv_bfloat16* __restrict__ A, const __nv_bfloat16* __restrict__ B,
    const float* __restrict__ bias, float* __restrict__ Cf,
    __nv_bfloat16* __restrict__ Cb, int M, int N, int K)
{
    extern __shared__ char smb[];
    const int tid = threadIdx.x, lane = tid & 31, wid = tid >> 5;
    const int wm = wid >> 1, wn = wid & 1;
    const int m0 = blockIdx.y * 128, n0 = blockIdx.x * 128;
    const int g = lane >> 2, tg = lane & 3;
    const int S = K >> 6;

    float acc[2][8][4];
#pragma unroll
    for (int a = 0; a < 2; a++)
#pragma unroll
        for (int b = 0; b < 8; b++)
#pragma unroll
            for (int c = 0; c < 4; c++) acc[a][b][c] = 0.f;

    issue_big(smb, 0, 0, A, B, M, N, K, m0, n0); CP_COMMIT;
    if (S > 1) issue_big(smb, 1, 64, A, B, M, N, K, m0, n0);
    CP_COMMIT;

    for (int si = 0; si < S; si++) {
        CP_WAIT1;
        __syncthreads();
        if (si + 2 < S) issue_big(smb, (si + 2) % 3, (si + 2) << 6, A, B, M, N, K, m0, n0);
        CP_COMMIT;
        __nv_bfloat16 (*As)[BKP] = (__nv_bfloat16(*)[BKP])((__nv_bfloat16*)smb + (si % 3) * (2 * 128 * BKP));
        __nv_bfloat16 (*Bs)[BKP] = (__nv_bfloat16(*)[BKP])((__nv_bfloat16*)smb + (si % 3) * (2 * 128 * BKP) + 128 * BKP);
#pragma unroll
        for (int kt = 0; kt < 4; kt++) {
            const int c0 = kt * 16 + tg * 2;
            unsigned af[2][4];
#pragma unroll
            for (int mt = 0; mt < 2; mt++) {
                int r = wm * 32 + mt * 16 + g;
                af[mt][0] = *(const unsigned*)&As[r][c0];
                af[mt][1] = *(const unsigned*)&As[r + 8][c0];
                af[mt][2] = *(const unsigned*)&As[r][c0 + 8];
                af[mt][3] = *(const unsigned*)&As[r + 8][c0 + 8];
            }
#pragma unroll
            for (int nt = 0; nt < 8; nt++) {
                int n = wn * 64 + nt * 8 + g;
                unsigned bf[2];
                bf[0] = *(const unsigned*)&Bs[n][c0];
                bf[1] = *(const unsigned*)&Bs[n][c0 + 8];
                mma_bf16(acc[0][nt], af[0], bf);
                mma_bf16(acc[1][nt], af[1], bf);
            }
        }
    }

#pragma unroll
    for (int mt = 0; mt < 2; mt++) {
#pragma unroll
        for (int nt = 0; nt < 8; nt++) {
            int r = m0 + wm * 32 + mt * 16 + g;
            int c = n0 + wn * 64 + nt * 8 + tg * 2;
            float* a = acc[mt][nt];
            if (EPI == 0) {
                float b0 = (c < N) ? bias[c] : 0.f;
                float b1 = (c + 1 < N) ? bias[c + 1] : 0.f;
                if (r < M) {
                    if (c < N)     Cf[(long long)r * N + c]     = a[0] + b0;
                    if (c + 1 < N) Cf[(long long)r * N + c + 1] = a[1] + b1;
                }
                if (r + 8 < M) {
                    if (c < N)     Cf[(long long)(r + 8) * N + c]     = a[2] + b0;
                    if (c + 1 < N) Cf[(long long)(r + 8) * N + c + 1] = a[3] + b1;
                }
            } else {
                float b0 = bias[c], b1 = bias[c + 1];
                __nv_bfloat162 v0 = __floats2bfloat162_rn(tanhf(a[0] + b0), tanhf(a[1] + b1));
                __nv_bfloat162 v1 = __floats2bfloat162_rn(tanhf(a[2] + b0), tanhf(a[3] + b1));
                *(__nv_bfloat162*)(Cb + (long long)r * N + c) = v0;
                *(__nv_bfloat162*)(Cb + (long long)(r + 8) * N + c) = v1;
            }
        }
    }
}

// ---------------------------------------------------------------- barrier (round-8 simple)
__device__ __forceinline__ void gbar(int e) {
    __syncthreads();
    if (threadIdx.x == 0) {
        __threadfence();
        unsigned old = atomicAdd(&g_arrive, 1u);
        if (old == (unsigned)e * NBLK + (NBLK - 1)) {
            atomicExch(&g_release, (unsigned)(e + 1));
        } else {
            unsigned r;
            do { asm volatile("ld.global.cg.u32 %0, [%1];" : "=r"(r) : "l"(&g_release)); }
            while (r < (unsigned)(e + 1));
        }
        __threadfence();
    }
    __syncthreads();
}

// ---------------------------------------------------------------- tile GEMM
template <int AKIND, int NT>
__device__ __forceinline__ void issue_chunk(
    char* smraw, int slot, int kc, int K,
    const __nv_bfloat16* A0, const __nv_bfloat16* A1,
    const __nv_bfloat16* B, int n0)
{
    constexpr int ASZ = 32 * 264;
    constexpr int STE = ASZ + NT * 8 * 264;
    __nv_bfloat16* smA = (__nv_bfloat16*)smraw + slot * STE;
    __nv_bfloat16* smB = smA + ASZ;
    const int tid = threadIdx.x;
    const int kbase = kc << 8;
    const int region = kbase >> 10;
    const int koff = kbase & 1023;
#pragma unroll
    for (int j = 0; j < 4; j++) {
        int u = tid + j * 256;
        int r = u >> 5, c = (u & 31) << 3;
        const __nv_bfloat16* src;
        if (AKIND == 0) src = A0 + r * 1024 + kbase + c;
        else src = (region == 0 ? A0 : A1) + r * 1024 + koff + c;
        cpa16(sptr(smA + r * 264 + c), src);
    }
#pragma unroll
    for (int j = 0; j < NT; j++) {
        int u = tid + j * 256;
        int r = u >> 5, c = (u & 31) << 3;
        cpa16(sptr(smB + r * 264 + c), B + (long long)(n0 + r) * K + kbase + c);
    }
}

template <int AKIND, int EPI, int NT, bool ZALL, bool HASEB>
__device__ void gtile(char* smraw, int n0, int K,
                      const __nv_bfloat16* __restrict__ B, const float* __restrict__ bias,
                      const __nv_bfloat16* A0, const __nv_bfloat16* A1,
                      __nv_bfloat16* outb, float* cst, __nv_bfloat16* znew,
                      __nv_bfloat16* zallp, int step, const float* eb)
{
    constexpr int ASZ = 32 * 264;
    constexpr int STE = ASZ + NT * 8 * 264;
    constexpr int NW = 32 * NT * 8;
    const int tid = threadIdx.x, lane = tid & 31, wid = tid >> 5;
    const int g = lane >> 2, tg = lane & 3;
    const int S = K >> 8;

    float acc[2][NT][4];
#pragma unroll
    for (int a = 0; a < 2; a++)
#pragma unroll
        for (int b = 0; b < NT; b++)
#pragma unroll
            for (int c = 0; c < 4; c++) acc[a][b][c] = 0.f;

#pragma unroll
    for (int st = 0; st < 3; st++) {
        if (st < S) issue_chunk<AKIND, NT>(smraw, st, st, K, A0, A1, B, n0);
        CP_COMMIT;
    }

    for (int si = 0; si < S; si++) {
        CP_WAIT2;
        __syncthreads();
        int nx = si + 3;
        if (nx < S) issue_chunk<AKIND, NT>(smraw, nx & 3, nx, K, A0, A1, B, n0);
        CP_COMMIT;
        __nv_bfloat16 (*As)[264] = (__nv_bfloat16(*)[264])((__nv_bfloat16*)smraw + (si & 3) * STE);
        __nv_bfloat16 (*Bs)[264] = (__nv_bfloat16(*)[264])((__nv_bfloat16*)smraw + (si & 3) * STE + ASZ);
#pragma unroll
        for (int ks = 0; ks < 2; ks++) {
            const int c0 = wid * 32 + ks * 16 + tg * 2;
            unsigned af[2][4];
#pragma unroll
            for (int mt = 0; mt < 2; mt++) {
                int r = mt * 16 + g;
                af[mt][0] = *(const unsigned*)&As[r][c0];
                af[mt][1] = *(const unsigned*)&As[r + 8][c0];
                af[mt][2] = *(const unsigned*)&As[r][c0 + 8];
                af[mt][3] = *(const unsigned*)&As[r + 8][c0 + 8];
            }
#pragma unroll
            for (int nt = 0; nt < NT; nt++) {
                int n = nt * 8 + g;
                unsigned bf[2];
                bf[0] = *(const unsigned*)&Bs[n][c0];
                bf[1] = *(const unsigned*)&Bs[n][c0 + 8];
                mma_bf16(acc[0][nt], af[0], bf);
                mma_bf16(acc[1][nt], af[1], bf);
            }
        }
    }
    __syncthreads();

    float* Pred = (float*)smraw;
    {
        int base = wid * NW;
#pragma unroll
        for (int mt = 0; mt < 2; mt++)
#pragma unroll
            for (int nt = 0; nt < NT; nt++) {
                int r = mt * 16 + g, cl = nt * 8 + tg * 2;
                Pred[base + r * (NT * 8) + cl]           = acc[mt][nt][0];
                Pred[base + r * (NT * 8) + cl + 1]       = acc[mt][nt][1];
                Pred[base + (r + 8) * (NT * 8) + cl]     = acc[mt][nt][2];
                Pred[base + (r + 8) * (NT * 8) + cl + 1] = acc[mt][nt][3];
            }
    }
    __syncthreads();

    if (EPI == 0) {
        for (int o = tid; o < NW; o += 256) {
            int r = o / (NT * 8), c = o % (NT * 8);
            float sum = 0.f;
#pragma unroll
            for (int w = 0; w < 8; w++) sum += Pred[w * NW + o];
            outb[r * 1024 + n0 + c] = __float2bfloat16(tanhf(sum + bias[n0 + c]));
        }
    } else {
        int b = tid >> 3, ul = tid & 7;
        float gv[4];
#pragma unroll
        for (int gate = 0; gate < 4; gate++) {
            int col = ul * 4 + gate;
            float sum = 0.f;
#pragma unroll
            for (int w = 0; w < 8; w++) sum += Pred[w * 1024 + b * 32 + col];
            float bb = HASEB ? eb[b * 4096 + n0 + col] : bias[n0 + col];
            gv[gate] = sum + bb;
        }
        int u = (n0 >> 2) + ul;
        int gid = b * 1024 + u;
        float cv = sigm(gv[1]) * cst[gid] + sigm(gv[0]) * tanhf(gv[2]);
        float h = sigm(gv[3]) * tanhf(cv);
        cst[gid] = cv;
        znew[gid] = __float2bfloat16(h);
        if (ZALL) zallp[(long long)(step * 32 + b) * 2048 + u] = __float2bfloat16(h);
    }
    __syncthreads();
}

// ---------------------------------------------------------------- attention
// 148 blocks: b<20 -> 5 chunks of 80 t; b>=20 -> 4 chunks of 100 t. hlen-skip.
__device__ void phase_epc(char* smraw, int s, const int* __restrict__ hlens) {
    const int bid = blockIdx.x;
    int b, t0, tlen, ncs, base;
    if (bid < 100) { b = bid / 5; t0 = (bid % 5) * 80; tlen = 80; ncs = 5; base = b * 5; }
    else { int u = bid - 100; b = 20 + (u >> 2); t0 = (u & 3) * 100; tlen = 100; ncs = 4; base = 100 + (b - 20) * 4; }

    const int tid = threadIdx.x, lane = tid & 31, wid = tid >> 5;
    float* dqs = (float*)smraw;
    float* ws  = dqs + 1024;
    float* red = ws + 104;
    float* pcr = red + 256;
    int*   flg = (int*)(pcr + 8192);

    const uint4* dqp = (const uint4*)(g_dqb + b * 1024);
    for (int j = tid; j < 128; j += 256) {
        uint4 v = __ldcg(dqp + j);
        const __nv_bfloat162* h = (const __nv_bfloat162*)&v;
#pragma unroll
        for (int k = 0; k < 4; k++) {
            float2 f = __bfloat1622float2(h[k]);
            dqs[j * 8 + k * 2]     = f.x;
            dqs[j * 8 + k * 2 + 1] = f.y;
        }
    }
    __syncthreads();

    const int hl = hlens[b];
    for (int bs = wid * 2; bs < tlen; bs += 16) {
        int t = t0 + bs;
        if (t >= hl) {
            if (lane == 0) { ws[bs] = NEGBIG; ws[bs + 1] = NEGBIG; }
            continue;
        }
        const __nv_bfloat16* r1 = g_preb + ((long long)b * 400 + t) * 1024 + lane * 8;
        const __nv_bfloat16* r2 = r1 + 1024;
        float a1 = 0.f, a2 = 0.f, a3 = 0.f, a4 = 0.f;
#pragma unroll
        for (int q = 0; q < 4; q++) {
            uint4 v1 = *(const uint4*)(r1 + q * 256);
            uint4 v2 = *(const uint4*)(r2 + q * 256);
            const __nv_bfloat162* h1 = (const __nv_bfloat162*)&v1;
            const __nv_bfloat162* h2 = (const __nv_bfloat162*)&v2;
#pragma unroll
            for (int k = 0; k < 4; k++) {
                float2 d = *(const float2*)(dqs + q * 256 + lane * 8 + k * 2);
                float2 f1 = __bfloat1622float2(h1[k]);
                float2 f2 = __bfloat1622float2(h2[k]);
                a1 = fmaf(f1.x, d.x, a1); a2 = fmaf(f1.y, d.y, a2);
                a3 = fmaf(f2.x, d.x, a3); a4 = fmaf(f2.y, d.y, a4);
            }
        }
        float s1 = a1 + a2, s2 = a3 + a4;
#pragma unroll
        for (int off = 16; off; off >>= 1) {
            s1 += __shfl_xor_sync(0xffffffffu, s1, off);
            s2 += __shfl_xor_sync(0xffffffffu, s2, off);
        }
        if (lane == 0) {
            ws[bs]     = 2.f * s1;
            ws[bs + 1] = (t + 1 < hl) ? 2.f * s2 : NEGBIG;
        }
    }
    __syncthreads();

    float lm = NEGBIG;
    for (int i = tid; i < tlen; i += 256) lm = fmaxf(lm, ws[i]);
    red[tid] = lm; __syncthreads();
    for (int st = 128; st; st >>= 1) { if (tid < st) red[tid] = fmaxf(red[tid], red[tid + st]); __syncthreads(); }
    const float m = red[0]; __syncthreads();
    float ls = 0.f;
    for (int i = tid; i < tlen; i += 256) { float w = expf(ws[i] - m); ws[i] = w; ls += w; }
    red[tid] = ls; __syncthreads();
    for (int st = 128; st; st >>= 1) { if (tid < st) red[tid] += red[tid + st]; __syncthreads(); }
    const float sl = red[0];
    __syncthreads();

    float pacc[32];
#pragma unroll
    for (int i = 0; i < 32; i++) pacc[i] = 0.f;
    for (int bs = wid * 2; bs < tlen; bs += 16) {
        if (t0 + bs >= hl) continue;  // w==0 for both rows
        float w1 = ws[bs], w2 = ws[bs + 1];
        const __nv_bfloat16* r1 = g_hsb + ((long long)b * 400 + t0 + bs) * 1024 + lane * 8;
        const __nv_bfloat16* r2 = r1 + 1024;
#pragma unroll
        for (int q = 0; q < 4; q++) {
            uint4 v1 = *(const uint4*)(r1 + q * 256);
            uint4 v2 = *(const uint4*)(r2 + q * 256);
            const __nv_bfloat162* h1 = (const __nv_bfloat162*)&v1;
            const __nv_bfloat162* h2 = (const __nv_bfloat162*)&v2;
#pragma unroll
            for (int k = 0; k < 4; k++) {
                float2 f1 = __bfloat1622float2(h1[k]);
                float2 f2 = __bfloat1622float2(h2[k]);
                int o = q * 8 + k * 2;
                pacc[o]     = fmaf(w1, f1.x, fmaf(w2, f2.x, pacc[o]));
                pacc[o + 1] = fmaf(w1, f1.y, fmaf(w2, f2.y, pacc[o + 1]));
            }
        }
    }
#pragma unroll
    for (int q = 0; q < 4; q++)
#pragma unroll
        for (int j = 0; j < 8; j++)
            pcr[wid * 1024 + q * 256 + lane * 8 + j] = pacc[q * 8 + j];
    __syncthreads();
    for (int col = tid; col < 1024; col += 256) {
        float a = 0.f;
#pragma unroll
        for (int w = 0; w < 8; w++) a += pcr[w * 1024 + col];
        g_pc[bid * 1024 + col] = a;
    }
    if (tid == 0) { g_ms[bid * 2] = m; g_ms[bid * 2 + 1] = sl; }
    __syncthreads();

    if (tid == 0) {
        __threadfence();
        unsigned old = atomicAdd(&g_cmb[b], 1u);
        *flg = (old == (unsigned)(s * ncs + ncs - 1)) ? 1 : 0;
    }
    __syncthreads();
    if (*flg) {
        float mi[5], si[5];
        for (int i = 0; i < ncs; i++) {
            mi[i] = __ldcg(&g_ms[(base + i) * 2]);
            si[i] = __ldcg(&g_ms[(base + i) * 2 + 1]);
        }
        float M = NEGBIG;
        for (int i = 0; i < ncs; i++) M = fmaxf(M, mi[i]);
        float sc[5], Ssum = 0.f;
        for (int i = 0; i < ncs; i++) { sc[i] = expf(mi[i] - M); Ssum += sc[i] * si[i]; }
        float inv = 1.f / Ssum;
        for (int col = tid; col < 1024; col += 256) {
            float a = 0.f;
            for (int i = 0; i < ncs; i++) a += sc[i] * __ldcg(&g_pc[(base + i) * 1024 + col]);
            __nv_bfloat16 v = __float2bfloat16(a * inv);
            g_attb[b * 1024 + col] = v;
            g_zallb[((long long)s * 32 + b) * 2048 + 1024 + col] = v;
        }
    }
    __syncthreads();
}

// ---------------------------------------------------------------- main loop
// Phase 1: [g1(s-1) on 0..127 || dq(s) on 128..143 -> flag] then ALL blocks
// wait dq-flag and run attn(s). Barrier. Phase 2: g0(s) on 0..127. Barrier.
__global__ void __launch_bounds__(256, 1) k_loop(const int* __restrict__ hlens,
                                                 const float* __restrict__ bdec) {
    extern __shared__ char sm[];
    const int bid = blockIdx.x;
    int ep = 0;

    for (int s = 0; s <= 101; s++) {
        const int p = s & 1;
        // Phase 1a: g1(s-1) || dq(s)
        if (bid < 128) {
            if (s >= 1)
                gtile<2, 1, 4, true, false>(sm, bid * 32, 2048, g_Wc1r, g_bs1r,
                                            g_z0s[p], g_z1s[1 - p],
                                            nullptr, g_c1, g_z1s[p], g_zallb, s - 1, nullptr);
        } else if (bid < 144) {
            if (s <= 100) {
                gtile<0, 0, 8, false, false>(sm, (bid - 128) * 64, 1024, g_Wdecb, bdec,
                                             g_z0s[p], nullptr,
                                             g_dqb, nullptr, nullptr, nullptr, s, nullptr);
                if (threadIdx.x == 0) {
                    __threadfence();
                    atomicAdd(&g_dqf, 1u);
                }
            }
        }
        // Phase 1b: wait for dq, then attention on all 148 blocks
        if (s <= 100) {
            if (threadIdx.x == 0) {
                unsigned r;
                do { asm volatile("ld.global.cg.u32 %0, [%1];" : "=r"(r) : "l"(&g_dqf)); }
                while (r < (unsigned)(16 * (s + 1)));
            }
            __syncthreads();
            phase_epc(sm, s, hlens);
        }
        gbar(ep); ep++;
        if (s == 101) break;

        // Phase 2: g0(s)
        if (bid < 128) {
            gtile<2, 1, 4, false, true>(sm, bid * 32, 2048, g_Wc0x, nullptr,
                                        g_attb, g_z0s[p],
                                        nullptr, g_c0, g_z0s[1 - p], nullptr, s,
                                        g_emb0 + (long long)s * 32 * 4096);
        }
        gbar(ep); ep++;
    }
}

// ---------------------------------------------------------------- CE
__global__ void k_ce(const void* __restrict__ ys) {
    int r = blockIdx.x;
    int l = r / BB, b = r % BB;
    const float* y = g_yall + (long long)r * VV;
    __shared__ float red[256];
    int tid = threadIdx.x;
    float lm = NEGBIG;
    for (int v = tid; v < VV; v += 256) lm = fmaxf(lm, y[v]);
    red[tid] = lm; __syncthreads();
    for (int s = 128; s > 0; s >>= 1) { if (tid < s) red[tid] = fmaxf(red[tid], red[tid + s]); __syncthreads(); }
    float m = red[0]; __syncthreads();
    float ls = 0.f;
    for (int v = tid; v < VV; v += 256) ls += expf(y[v] - m);
    red[tid] = ls; __syncthreads();
    for (int s = 128; s > 0; s >>= 1) { if (tid < s) red[tid] += red[tid + s]; __syncthreads(); }
    if (tid == 0) {
        int tgt = (l < LL) ? read_ys(ys, b * LL + l) : 4999;
        atomicAdd(&g_loss, logf(red[0]) + m - y[tgt]);
    }
}

__global__ void k_fin(float* out) {
    out[0] = g_loss * ((float)LL / (float)(L1 * BB));
}

// ---------------------------------------------------------------- launch
extern "C" void kernel_launch(void* const* d_in, const int* in_sizes, int n_in,
                              void* d_out, int out_size) {
    const float* hs    = (const float*)d_in[0];
    const float* embed = (const float*)d_in[1];
    const float* Wenc  = (const float*)d_in[2];
    const float* benc  = (const float*)d_in[3];
    const float* Wdec  = (const float*)d_in[4];
    const float* bdec  = (const float*)d_in[5];
    const float* Wih0  = (const float*)d_in[6];
    const float* Whh0  = (const float*)d_in[7];
    const float* bih0  = (const float*)d_in[8];
    const float* bhh0  = (const float*)d_in[9];
    const float* Wih1  = (const float*)d_in[10];
    const float* Whh1  = (const float*)d_in[11];
    const float* bih1  = (const float*)d_in[12];
    const float* bhh1  = (const float*)d_in[13];
    const float* Wout  = (const float*)d_in[14];
    const float* bout  = (const float*)d_in[15];
    const int*   hlens = (const int*)d_in[16];
    const void*  ys    = (const void*)d_in[17];

    __nv_bfloat16 *hsb, *preb, *eysb, *Wencb, *Woutb, *Wc0e, *zallb;
    float *yall, *bs0r, *emb0;
    cudaGetSymbolAddress((void**)&hsb,   g_hsb);
    cudaGetSymbolAddress((void**)&preb,  g_preb);
    cudaGetSymbolAddress((void**)&eysb,  g_eysb);
    cudaGetSymbolAddress((void**)&Wencb, g_Wencb);
    cudaGetSymbolAddress((void**)&Woutb, g_Woutb);
    cudaGetSymbolAddress((void**)&Wc0e,  g_Wc0e);
    cudaGetSymbolAddress((void**)&zallb, g_zallb);
    cudaGetSymbolAddress((void**)&yall,  g_yall);
    cudaGetSymbolAddress((void**)&bs0r,  g_bs0r);
    cudaGetSymbolAddress((void**)&emb0,  g_emb0);

    static int smem_set = 0;
    if (!smem_set) {
        cudaFuncSetAttribute(k_loop, cudaFuncAttributeMaxDynamicSharedMemorySize, SMSZ);
        cudaFuncSetAttribute(mma_big<0>, cudaFuncAttributeMaxDynamicSharedMemorySize, BIG_SMEM);
        cudaFuncSetAttribute(mma_big<1>, cudaFuncAttributeMaxDynamicSharedMemorySize, BIG_SMEM);
        smem_set = 1;
    }

    k_prep_all<<<296, 256>>>(hs, embed, Wenc, Wdec, Wout,
                             Wih0, Whh0, Wih1, Whh1,
                             bih0, bhh0, bih1, bhh1, ys);

    mma_big<0><<<dim3(4096 / 128, (L1 * BB + 127) / 128), 256, BIG_SMEM>>>(
        eysb, Wc0e, bs0r, emb0, nullptr, L1 * BB, 4096, 1024);

    mma_big<1><<<dim3(DD / 128, BB * TT / 128), 256, BIG_SMEM>>>(
        hsb, Wencb, benc, nullptr, preb, BB * TT, DD, DD);

    k_loop<<<NBLK, 256, SMSZ>>>(hlens, bdec);

    mma_big<0><<<dim3((VV + 127) / 128, (L1 * BB + 127) / 128), 256, BIG_SMEM>>>(
        zallb, Woutb, bout, yall, nullptr, L1 * BB, VV, 2048);

    k_ce<<<L1 * BB, 256>>>(ys);
    k_fin<<<1, 1>>>((float*)d_out);
}

// round 12
// speedup vs baseline: 1.1986x; 1.0375x over previous
#include <cuda_runtime.h>
#include <cuda_bf16.h>

#define BB 32
#define TT 400
#define DD 1024
#define VV 5000
#define LL 100
#define L1 101
#define NEGBIG -1e30f
#define NBLK 148
// smem: pinned Wc0x tile [8 chunks][32][264] bf16 = 135168B, stream region 69632B
#define PIN 135168
#define SMSZ 204800
#define BIG_SMEM 110592

__device__ __align__(16) __nv_bfloat16 g_hsb [BB * TT * DD];
__device__ __align__(16) __nv_bfloat16 g_preb[BB * TT * DD];
__device__ __align__(16) __nv_bfloat16 g_eysb[L1 * BB * DD];
__device__ __align__(16) __nv_bfloat16 g_Wencb[DD * DD];
__device__ __align__(16) __nv_bfloat16 g_Wdecb[DD * DD];
__device__ __align__(16) __nv_bfloat16 g_Woutb[VV * 2048];
__device__ __align__(16) __nv_bfloat16 g_Wc0e[4096 * 1024];
__device__ __align__(16) __nv_bfloat16 g_Wc0x[4096 * 2048];
__device__ __align__(16) __nv_bfloat16 g_Wc1r[4096 * 2048];
__device__ __align__(16) float g_bs0r[4096];
__device__ __align__(16) float g_bs1r[4096];
__device__ __align__(16) float g_emb0[(long long)L1 * BB * 4096];
__device__ __align__(16) __nv_bfloat16 g_dqb[BB * DD];
__device__ __align__(16) __nv_bfloat16 g_attb[BB * DD];
__device__ __align__(16) __nv_bfloat16 g_z0s[2][BB * DD];
__device__ __align__(16) __nv_bfloat16 g_z1s[2][BB * DD];
__device__ __align__(16) float g_c0[BB * DD];
__device__ __align__(16) float g_c1[BB * DD];
__device__ __align__(16) float g_pc[148 * 1024];
__device__ __align__(16) float g_ms[304];
__device__ unsigned g_cmb[32];
__device__ __align__(16) __nv_bfloat16 g_zallb[L1 * BB * 2048];
__device__ __align__(16) float g_yall[(long long)L1 * BB * VV];
__device__ float g_loss;
__device__ int g_i64;
__device__ unsigned g_arrive;
__device__ unsigned g_release;
__device__ unsigned g_dqf;

__device__ __forceinline__ float sigm(float x) { return 1.0f / (1.0f + expf(-x)); }
__device__ __forceinline__ int read_ys(const void* ys, int i) {
    return g_i64 ? (int)((const long long*)ys)[i] : ((const int*)ys)[i];
}
__device__ __forceinline__ unsigned sptr(const void* p) {
    unsigned r;
    asm("{.reg .u64 t; cvta.to.shared.u64 t, %1; cvt.u32.u64 %0, t;}" : "=r"(r) : "l"(p));
    return r;
}
__device__ __forceinline__ void cpa16(unsigned s, const void* g) {
    asm volatile("cp.async.cg.shared.global [%0], [%1], 16;" :: "r"(s), "l"(g));
}
#define CP_COMMIT asm volatile("cp.async.commit_group;")
#define CP_WAIT2  asm volatile("cp.async.wait_group 2;")
#define CP_WAIT1  asm volatile("cp.async.wait_group 1;")
#define CP_WAIT0  asm volatile("cp.async.wait_group 0;")

__device__ __forceinline__ unsigned pack2(float a, float b) {
    __nv_bfloat162 p = __floats2bfloat162_rn(a, b);
    return *(unsigned*)&p;
}

// ---------------------------------------------------------------- fused prologue
__global__ void k_prep_all(
    const float* __restrict__ hs, const float* __restrict__ embed,
    const float* __restrict__ Wenc, const float* __restrict__ Wdec,
    const float* __restrict__ Wout,
    const float* __restrict__ Wih0, const float* __restrict__ Whh0,
    const float* __restrict__ Wih1, const float* __restrict__ Whh1,
    const float* __restrict__ bih0, const float* __restrict__ bhh0,
    const float* __restrict__ bih1, const float* __restrict__ bhh1,
    const void* __restrict__ ys)
{
    __shared__ int s_i64;
    const int tid = threadIdx.x;
    if (tid == 0) {
        const int* w = (const int*)ys;
        int f = 1;
        for (int j = 1; j < 64; j += 2) if (w[j] != 0) f = 0;
        s_i64 = f;
    }
    __syncthreads();
    const int i64 = s_i64;
    const long long gi = (long long)blockIdx.x * blockDim.x + tid;
    const long long gn = (long long)gridDim.x * blockDim.x;

    {
        __nv_bfloat16 z = __float2bfloat16(0.f);
        for (long long j = gi; j < BB * DD; j += gn) {
            g_c0[j] = 0.f; g_c1[j] = 0.f;
            g_z0s[0][j] = z; g_z0s[1][j] = z;
            g_z1s[0][j] = z; g_z1s[1][j] = z;
        }
        for (long long j = gi; j < 4096; j += gn) {
            int u = (int)j >> 2, gate = (int)j & 3;
            int orow = gate * 1024 + u;
            g_bs0r[j] = bih0[orow] + bhh0[orow];
            g_bs1r[j] = bih1[orow] + bhh1[orow];
        }
        if (gi < 32) g_cmb[gi] = 0u;
        if (gi == 0) { g_loss = 0.f; g_arrive = 0u; g_release = 0u; g_dqf = 0u; g_i64 = i64; }
    }
    {
        const float4* s = (const float4*)hs;
        uint4* d = (uint4*)g_hsb;
        for (long long j = gi; j < 1638400LL; j += gn) {
            float4 a = s[2 * j], b = s[2 * j + 1];
            d[j] = make_uint4(pack2(a.x, a.y), pack2(a.z, a.w), pack2(b.x, b.y), pack2(b.z, b.w));
        }
    }
    {
        const float4* s = (const float4*)Wenc;
        uint4* d = (uint4*)g_Wencb;
        for (long long j = gi; j < 131072LL; j += gn) {
            float4 a = s[2 * j], b = s[2 * j + 1];
            d[j] = make_uint4(pack2(a.x, a.y), pack2(a.z, a.w), pack2(b.x, b.y), pack2(b.z, b.w));
        }
    }
    {
        const float4* s = (const float4*)Wdec;
        uint4* d = (uint4*)g_Wdecb;
        for (long long j = gi; j < 131072LL; j += gn) {
            float4 a = s[2 * j], b = s[2 * j + 1];
            d[j] = make_uint4(pack2(a.x, a.y), pack2(a.z, a.w), pack2(b.x, b.y), pack2(b.z, b.w));
        }
    }
    {
        const float4* s = (const float4*)Wout;
        uint4* d = (uint4*)g_Woutb;
        for (long long j = gi; j < 1280000LL; j += gn) {
            float4 a = s[2 * j], b = s[2 * j + 1];
            d[j] = make_uint4(pack2(a.x, a.y), pack2(a.z, a.w), pack2(b.x, b.y), pack2(b.z, b.w));
        }
    }
    {
        for (long long it = gi; it < 413696LL; it += gn) {
            int row = (int)(it >> 7), col = (int)(it & 127);
            int l = row >> 5, b = row & 31;
            int tok = 4999;
            if (l > 0) {
                int idx = b * LL + l - 1;
                tok = i64 ? (int)((const long long*)ys)[idx] : ((const int*)ys)[idx];
            }
            float4 v = ((const float4*)(embed + (long long)tok * 1024))[col];
            ((uint2*)(g_eysb + (long long)row * 1024))[col] = make_uint2(pack2(v.x, v.y), pack2(v.z, v.w));
        }
    }
    {
        for (long long j4 = gi; j4 < 1048576LL; j4 += gn) {
            long long j = j4 * 4;
            int r = (int)(j >> 10), c = (int)(j & 1023);
            long long orow = (r & 3) * 1024 + (r >> 2);
            float4 v = *(const float4*)(Wih0 + orow * 2048 + c);
            *(uint2*)(g_Wc0e + j) = make_uint2(pack2(v.x, v.y), pack2(v.z, v.w));
        }
    }
    {
        for (long long j4 = gi; j4 < 2097152LL; j4 += gn) {
            long long j = j4 * 4;
            int r = (int)(j >> 11), c = (int)(j & 2047);
            long long orow = (r & 3) * 1024 + (r >> 2);
            float4 v = (c < 1024) ? *(const float4*)(Wih0 + orow * 2048 + 1024 + c)
                                  : *(const float4*)(Whh0 + orow * 1024 + (c - 1024));
            *(uint2*)(g_Wc0x + j) = make_uint2(pack2(v.x, v.y), pack2(v.z, v.w));
        }
    }
    {
        for (long long j4 = gi; j4 < 2097152LL; j4 += gn) {
            long long j = j4 * 4;
            int r = (int)(j >> 11), c = (int)(j & 2047);
            long long orow = (r & 3) * 1024 + (r >> 2);
            float4 v = (c < 1024) ? *(const float4*)(Wih1 + orow * 1024 + c)
                                  : *(const float4*)(Whh1 + orow * 1024 + (c - 1024));
            *(uint2*)(g_Wc1r + j) = make_uint2(pack2(v.x, v.y), pack2(v.z, v.w));
        }
    }
}

__device__ __forceinline__ void mma_bf16(float* d, const unsigned* a, const unsigned* b) {
    asm volatile(
        "mma.sync.aligned.m16n8k16.row.col.f32.bf16.bf16.f32 "
        "{%0,%1,%2,%3}, {%4,%5,%6,%7}, {%8,%9}, {%0,%1,%2,%3};\n"
        : "+f"(d[0]), "+f"(d[1]), "+f"(d[2]), "+f"(d[3])
        : "r"(a[0]), "r"(a[1]), "r"(a[2]), "r"(a[3]), "r"(b[0]), "r"(b[1]));
}

// ---------------------------------------------------------------- big GEMM
#define BKP 72
__device__ __forceinline__ void issue_big(
    char* smb, int slot, int k0,
    const __nv_bfloat16* A, const __nv_bfloat16* B,
    int M, int N, int K, int m0, int n0)
{
    __nv_bfloat16* smA = (__nv_bfloat16*)smb + slot * (2 * 128 * BKP);
    __nv_bfloat16* smB = smA + 128 * BKP;
    const int tid = threadIdx.x;
#pragma unroll
    for (int j = 0; j < 4; j++) {
        int idx = tid + j * 256;
        int r = idx >> 3, c = (idx & 7) * 8;
        int m = m0 + r; if (m >= M) m = 0;
        cpa16(sptr(smA + r * BKP + c), A + (long long)m * K + k0 + c);
        int n = n0 + r; if (n >= N) n = 0;
        cpa16(sptr(smB + r * BKP + c), B + (long long)n * K + k0 + c);
    }
}

template <int EPI>
__global__ __launch_bounds__(256) void mma_big(
    const __nv_bfloat16* __restrict__ A, const __nv_bfloat16* __restrict__ B,
    const float* __restrict__ bias, float* __restrict__ Cf,
    __nv_bfloat16* __restrict__ Cb, int M, int N, int K)
{
    extern __shared__ char smb[];
    const int tid = threadIdx.x, lane = tid & 31, wid = tid >> 5;
    const int wm = wid >> 1, wn = wid & 1;
    const int m0 = blockIdx.y * 128, n0 = blockIdx.x * 128;
    const int g = lane >> 2, tg = lane & 3;
    const int S = K >> 6;

    float acc[2][8][4];
#pragma unroll
    for (int a = 0; a < 2; a++)
#pragma unroll
        for (int b = 0; b < 8; b++)
#pragma unroll
            for (int c = 0; c < 4; c++) acc[a][b][c] = 0.f;

    issue_big(smb, 0, 0, A, B, M, N, K, m0, n0); CP_COMMIT;
    if (S > 1) issue_big(smb, 1, 64, A, B, M, N, K, m0, n0);
    CP_COMMIT;

    for (int si = 0; si < S; si++) {
        CP_WAIT1;
        __syncthreads();
        if (si + 2 < S) issue_big(smb, (si + 2) % 3, (si + 2) << 6, A, B, M, N, K, m0, n0);
        CP_COMMIT;
        __nv_bfloat16 (*As)[BKP] = (__nv_bfloat16(*)[BKP])((__nv_bfloat16*)smb + (si % 3) * (2 * 128 * BKP));
        __nv_bfloat16 (*Bs)[BKP] = (__nv_bfloat16(*)[BKP])((__nv_bfloat16*)smb + (si % 3) * (2 * 128 * BKP) + 128 * BKP);
#pragma unroll
        for (int kt = 0; kt < 4; kt++) {
            const int c0 = kt * 16 + tg * 2;
            unsigned af[2][4];
#pragma unroll
            for (int mt = 0; mt < 2; mt++) {
                int r = wm * 32 + mt * 16 + g;
                af[mt][0] = *(const unsigned*)&As[r][c0];
                af[mt][1] = *(const unsigned*)&As[r + 8][c0];
                af[mt][2] = *(const unsigned*)&As[r][c0 + 8];
                af[mt][3] = *(const unsigned*)&As[r + 8][c0 + 8];
            }
#pragma unroll
            for (int nt = 0; nt < 8; nt++) {
                int n = wn * 64 + nt * 8 + g;
                unsigned bf[2];
                bf[0] = *(const unsigned*)&Bs[n][c0];
                bf[1] = *(const unsigned*)&Bs[n][c0 + 8];
                mma_bf16(acc[0][nt], af[0], bf);
                mma_bf16(acc[1][nt], af[1], bf);
            }
        }
    }

#pragma unroll
    for (int mt = 0; mt < 2; mt++) {
#pragma unroll
        for (int nt = 0; nt < 8; nt++) {
            int r = m0 + wm * 32 + mt * 16 + g;
            int c = n0 + wn * 64 + nt * 8 + tg * 2;
            float* a = acc[mt][nt];
            if (EPI == 0) {
                float b0 = (c < N) ? bias[c] : 0.f;
                float b1 = (c + 1 < N) ? bias[c + 1] : 0.f;
                if (r < M) {
                    if (c < N)     Cf[(long long)r * N + c]     = a[0] + b0;
                    if (c + 1 < N) Cf[(long long)r * N + c + 1] = a[1] + b1;
                }
                if (r + 8 < M) {
                    if (c < N)     Cf[(long long)(r + 8) * N + c]     = a[2] + b0;
                    if (c + 1 < N) Cf[(long long)(r + 8) * N + c + 1] = a[3] + b1;
                }
            } else {
                float b0 = bias[c], b1 = bias[c + 1];
                __nv_bfloat162 v0 = __floats2bfloat162_rn(tanhf(a[0] + b0), tanhf(a[1] + b1));
                __nv_bfloat162 v1 = __floats2bfloat162_rn(tanhf(a[2] + b0), tanhf(a[3] + b1));
                *(__nv_bfloat162*)(Cb + (long long)r * N + c) = v0;
                *(__nv_bfloat162*)(Cb + (long long)(r + 8) * N + c) = v1;
            }
        }
    }
}

// ---------------------------------------------------------------- barrier
__device__ __forceinline__ void gbar(int e) {
    __syncthreads();
    if (threadIdx.x == 0) {
        __threadfence();
        unsigned old = atomicAdd(&g_arrive, 1u);
        if (old == (unsigned)e * NBLK + (NBLK - 1)) {
            atomicExch(&g_release, (unsigned)(e + 1));
        } else {
            unsigned r;
            do { asm volatile("ld.global.cg.u32 %0, [%1];" : "=r"(r) : "l"(&g_release)); }
            while (r < (unsigned)(e + 1));
        }
        __threadfence();
    }
    __syncthreads();
}

// ---------------------------------------------------------------- LSTM epilogue (NT=4 tiles)
template <bool ZALL, bool HASEB>
__device__ __forceinline__ void lstm_epi(float* Pred, int n0, const float* bias,
                                         float* cst, __nv_bfloat16* znew,
                                         __nv_bfloat16* zallp, int step, const float* eb)
{
    const int tid = threadIdx.x;
    int b = tid >> 3, ul = tid & 7;
    float gv[4];
#pragma unroll
    for (int gate = 0; gate < 4; gate++) {
        int col = ul * 4 + gate;
        float sum = 0.f;
#pragma unroll
        for (int w = 0; w < 8; w++) sum += Pred[w * 1024 + b * 32 + col];
        float bb = HASEB ? eb[b * 4096 + n0 + col] : bias[n0 + col];
        gv[gate] = sum + bb;
    }
    int u = (n0 >> 2) + ul;
    int gid = b * 1024 + u;
    float cv = sigm(gv[1]) * cst[gid] + sigm(gv[0]) * tanhf(gv[2]);
    float h = sigm(gv[3]) * tanhf(cv);
    cst[gid] = cv;
    znew[gid] = __float2bfloat16(h);
    if (ZALL) zallp[(long long)(step * 32 + b) * 2048 + u] = __float2bfloat16(h);
}

// ---------------------------------------------------------------- dq tile GEMM (NT=8, K-chunk 256, streams A+B)
__device__ __forceinline__ void issue_dq(char* smraw, int slot, int kc,
                                         const __nv_bfloat16* A0, const __nv_bfloat16* B, int n0)
{
    constexpr int ASZ = 32 * 264;
    constexpr int STE = ASZ + 64 * 264;
    __nv_bfloat16* smA = (__nv_bfloat16*)smraw + slot * STE;
    __nv_bfloat16* smB = smA + ASZ;
    const int tid = threadIdx.x;
    const int kbase = kc << 8;
#pragma unroll
    for (int j = 0; j < 4; j++) {
        int u = tid + j * 256;
        int r = u >> 5, c = (u & 31) << 3;
        cpa16(sptr(smA + r * 264 + c), A0 + r * 1024 + kbase + c);
    }
#pragma unroll
    for (int j = 0; j < 8; j++) {
        int u = tid + j * 256;
        int r = u >> 5, c = (u & 31) << 3;
        cpa16(sptr(smB + r * 264 + c), B + (long long)(n0 + r) * 1024 + kbase + c);
    }
}

__device__ void gtile_dq(char* smraw, int n0, const __nv_bfloat16* __restrict__ B,
                         const float* __restrict__ bias, const __nv_bfloat16* A0,
                         __nv_bfloat16* outb)
{
    constexpr int ASZ = 32 * 264;
    constexpr int STE = ASZ + 64 * 264;
    constexpr int NW = 32 * 64;
    const int tid = threadIdx.x, lane = tid & 31, wid = tid >> 5;
    const int g = lane >> 2, tg = lane & 3;
    const int S = 4;

    float acc[2][8][4];
#pragma unroll
    for (int a = 0; a < 2; a++)
#pragma unroll
        for (int b = 0; b < 8; b++)
#pragma unroll
            for (int c = 0; c < 4; c++) acc[a][b][c] = 0.f;

#pragma unroll
    for (int st = 0; st < 3; st++) {
        if (st < S) issue_dq(smraw, st, st, A0, B, n0);
        CP_COMMIT;
    }

    for (int si = 0; si < S; si++) {
        CP_WAIT2;
        __syncthreads();
        int nx = si + 3;
        if (nx < S) issue_dq(smraw, nx & 3, nx, A0, B, n0);
        CP_COMMIT;
        __nv_bfloat16 (*As)[264] = (__nv_bfloat16(*)[264])((__nv_bfloat16*)smraw + (si & 3) * STE);
        __nv_bfloat16 (*Bs)[264] = (__nv_bfloat16(*)[264])((__nv_bfloat16*)smraw + (si & 3) * STE + ASZ);
#pragma unroll
        for (int ks = 0; ks < 2; ks++) {
            const int c0 = wid * 32 + ks * 16 + tg * 2;
            unsigned af[2][4];
#pragma unroll
            for (int mt = 0; mt < 2; mt++) {
                int r = mt * 16 + g;
                af[mt][0] = *(const unsigned*)&As[r][c0];
                af[mt][1] = *(const unsigned*)&As[r + 8][c0];
                af[mt][2] = *(const unsigned*)&As[r][c0 + 8];
                af[mt][3] = *(const unsigned*)&As[r + 8][c0 + 8];
            }
#pragma unroll
            for (int nt = 0; nt < 8; nt++) {
                int n = nt * 8 + g;
                unsigned bf[2];
                bf[0] = *(const unsigned*)&Bs[n][c0];
                bf[1] = *(const unsigned*)&Bs[n][c0 + 8];
                mma_bf16(acc[0][nt], af[0], bf);
                mma_bf16(acc[1][nt], af[1], bf);
            }
        }
    }
    __syncthreads();

    float* Pred = (float*)smraw;
    {
        int base = wid * NW;
#pragma unroll
        for (int mt = 0; mt < 2; mt++)
#pragma unroll
            for (int nt = 0; nt < 8; nt++) {
                int r = mt * 16 + g, cl = nt * 8 + tg * 2;
                Pred[base + r * 64 + cl]           = acc[mt][nt][0];
                Pred[base + r * 64 + cl + 1]       = acc[mt][nt][1];
                Pred[base + (r + 8) * 64 + cl]     = acc[mt][nt][2];
                Pred[base + (r + 8) * 64 + cl + 1] = acc[mt][nt][3];
            }
    }
    __syncthreads();

    for (int o = tid; o < NW; o += 256) {
        int r = o >> 6, c = o & 63;
        float sum = 0.f;
#pragma unroll
        for (int w = 0; w < 8; w++) sum += Pred[w * NW + o];
        outb[r * 1024 + n0 + c] = __float2bfloat16(tanhf(sum + bias[n0 + c]));
    }
    __syncthreads();
}

// ---------------------------------------------------------------- g1 tile GEMM (NT=4, K-chunk 128, streams A+B, 4 slots)
__device__ __forceinline__ void issue_g1(char* smraw, int slot, int kc,
                                         const __nv_bfloat16* A0, const __nv_bfloat16* A1,
                                         const __nv_bfloat16* B, int n0)
{
    constexpr int ASZ = 32 * 136;
    constexpr int STE = 2 * ASZ;
    __nv_bfloat16* smA = (__nv_bfloat16*)smraw + slot * STE;
    __nv_bfloat16* smB = smA + ASZ;
    const int tid = threadIdx.x;
    const int kbase = kc << 7;
    const int region = kbase >> 10;
    const int koff = kbase & 1023;
#pragma unroll
    for (int j = 0; j < 2; j++) {
        int u = tid + j * 256;
        int r = u >> 4, c = (u & 15) << 3;
        const __nv_bfloat16* src = (region == 0 ? A0 : A1) + r * 1024 + koff + c;
        cpa16(sptr(smA + r * 136 + c), src);
    }
#pragma unroll
    for (int j = 0; j < 2; j++) {
        int u = tid + j * 256;
        int r = u >> 4, c = (u & 15) << 3;
        cpa16(sptr(smB + r * 136 + c), B + (long long)(n0 + r) * 2048 + kbase + c);
    }
}

__device__ void gtile_g1(char* smraw, int n0, const __nv_bfloat16* __restrict__ B,
                         const float* __restrict__ bias,
                         const __nv_bfloat16* A0, const __nv_bfloat16* A1,
                         float* cst, __nv_bfloat16* znew, __nv_bfloat16* zallp, int step)
{
    constexpr int ASZ = 32 * 136;
    constexpr int STE = 2 * ASZ;
    const int tid = threadIdx.x, lane = tid & 31, wid = tid >> 5;
    const int g = lane >> 2, tg = lane & 3;
    const int S = 16;

    float acc[2][4][4];
#pragma unroll
    for (int a = 0; a < 2; a++)
#pragma unroll
        for (int b = 0; b < 4; b++)
#pragma unroll
            for (int c = 0; c < 4; c++) acc[a][b][c] = 0.f;

#pragma unroll
    for (int st = 0; st < 3; st++) {
        issue_g1(smraw, st, st, A0, A1, B, n0);
        CP_COMMIT;
    }

    for (int si = 0; si < S; si++) {
        CP_WAIT2;
        __syncthreads();
        int nx = si + 3;
        if (nx < S) issue_g1(smraw, nx & 3, nx, A0, A1, B, n0);
        CP_COMMIT;
        __nv_bfloat16 (*As)[136] = (__nv_bfloat16(*)[136])((__nv_bfloat16*)smraw + (si & 3) * STE);
        __nv_bfloat16 (*Bs)[136] = (__nv_bfloat16(*)[136])((__nv_bfloat16*)smraw + (si & 3) * STE + ASZ);
        const int c0 = wid * 16 + tg * 2;
        unsigned af[2][4];
#pragma unroll
        for (int mt = 0; mt < 2; mt++) {
            int r = mt * 16 + g;
            af[mt][0] = *(const unsigned*)&As[r][c0];
            af[mt][1] = *(const unsigned*)&As[r + 8][c0];
            af[mt][2] = *(const unsigned*)&As[r][c0 + 8];
            af[mt][3] = *(const unsigned*)&As[r + 8][c0 + 8];
        }
#pragma unroll
        for (int nt = 0; nt < 4; nt++) {
            int n = nt * 8 + g;
            unsigned bf[2];
            bf[0] = *(const unsigned*)&Bs[n][c0];
            bf[1] = *(const unsigned*)&Bs[n][c0 + 8];
            mma_bf16(acc[0][nt], af[0], bf);
            mma_bf16(acc[1][nt], af[1], bf);
        }
    }
    __syncthreads();

    float* Pred = (float*)smraw;
    {
        int base = wid * 1024;
#pragma unroll
        for (int mt = 0; mt < 2; mt++)
#pragma unroll
            for (int nt = 0; nt < 4; nt++) {
                int r = mt * 16 + g, cl = nt * 8 + tg * 2;
                Pred[base + r * 32 + cl]           = acc[mt][nt][0];
                Pred[base + r * 32 + cl + 1]       = acc[mt][nt][1];
                Pred[base + (r + 8) * 32 + cl]     = acc[mt][nt][2];
                Pred[base + (r + 8) * 32 + cl + 1] = acc[mt][nt][3];
            }
    }
    __syncthreads();
    lstm_epi<true, false>(Pred, n0, bias, cst, znew, zallp, step, nullptr);
    __syncthreads();
}

// ---------------------------------------------------------------- g0 tile GEMM (B pinned in smem, A streamed)
__device__ __forceinline__ void issue_g0a(char* strm, int slot, int kc,
                                          const __nv_bfloat16* A0, const __nv_bfloat16* A1)
{
    __nv_bfloat16* smA = (__nv_bfloat16*)strm + slot * (32 * 264);
    const int tid = threadIdx.x;
    const int kbase = kc << 8;
    const int region = kbase >> 10;
    const int koff = kbase & 1023;
#pragma unroll
    for (int j = 0; j < 4; j++) {
        int u = tid + j * 256;
        int r = u >> 5, c = (u & 31) << 3;
        const __nv_bfloat16* src = (region == 0 ? A0 : A1) + r * 1024 + koff + c;
        cpa16(sptr(smA + r * 264 + c), src);
    }
}

__device__ void gtile_g0pin(char* sm, int n0,
                            const __nv_bfloat16* A0, const __nv_bfloat16* A1,
                            float* cst, __nv_bfloat16* znew, int step, const float* eb)
{
    char* strm = sm + PIN;
    const int tid = threadIdx.x, lane = tid & 31, wid = tid >> 5;
    const int g = lane >> 2, tg = lane & 3;
    const int S = 8;

    float acc[2][4][4];
#pragma unroll
    for (int a = 0; a < 2; a++)
#pragma unroll
        for (int b = 0; b < 4; b++)
#pragma unroll
            for (int c = 0; c < 4; c++) acc[a][b][c] = 0.f;

#pragma unroll
    for (int st = 0; st < 3; st++) {
        issue_g0a(strm, st, st, A0, A1);
        CP_COMMIT;
    }

    for (int si = 0; si < S; si++) {
        CP_WAIT2;
        __syncthreads();
        int nx = si + 3;
        if (nx < S) issue_g0a(strm, nx & 3, nx, A0, A1);
        CP_COMMIT;
        __nv_bfloat16 (*As)[264] = (__nv_bfloat16(*)[264])((__nv_bfloat16*)strm + (si & 3) * (32 * 264));
        __nv_bfloat16 (*Bs)[264] = (__nv_bfloat16(*)[264])((__nv_bfloat16*)sm + si * (32 * 264));
#pragma unroll
        for (int ks = 0; ks < 2; ks++) {
            const int c0 = wid * 32 + ks * 16 + tg * 2;
            unsigned af[2][4];
#pragma unroll
            for (int mt = 0; mt < 2; mt++) {
                int r = mt * 16 + g;
                af[mt][0] = *(const unsigned*)&As[r][c0];
                af[mt][1] = *(const unsigned*)&As[r + 8][c0];
                af[mt][2] = *(const unsigned*)&As[r][c0 + 8];
                af[mt][3] = *(const unsigned*)&As[r + 8][c0 + 8];
            }
#pragma unroll
            for (int nt = 0; nt < 4; nt++) {
                int n = nt * 8 + g;
                unsigned bf[2];
                bf[0] = *(const unsigned*)&Bs[n][c0];
                bf[1] = *(const unsigned*)&Bs[n][c0 + 8];
                mma_bf16(acc[0][nt], af[0], bf);
                mma_bf16(acc[1][nt], af[1], bf);
            }
        }
    }
    __syncthreads();

    float* Pred = (float*)strm;
    {
        int base = wid * 1024;
#pragma unroll
        for (int mt = 0; mt < 2; mt++)
#pragma unroll
            for (int nt = 0; nt < 4; nt++) {
                int r = mt * 16 + g, cl = nt * 8 + tg * 2;
                Pred[base + r * 32 + cl]           = acc[mt][nt][0];
                Pred[base + r * 32 + cl + 1]       = acc[mt][nt][1];
                Pred[base + (r + 8) * 32 + cl]     = acc[mt][nt][2];
                Pred[base + (r + 8) * 32 + cl + 1] = acc[mt][nt][3];
            }
    }
    __syncthreads();
    lstm_epi<false, true>(Pred, n0, nullptr, cst, znew, nullptr, step, eb);
    __syncthreads();
}

// ---------------------------------------------------------------- attention (hlen-skip; scratch at sm+PIN)
__device__ void phase_epc(char* smraw, int s, const int* __restrict__ hlens) {
    const int bid = blockIdx.x;
    int b, t0, tlen, ncs, base;
    if (bid < 100) { b = bid / 5; t0 = (bid % 5) * 80; tlen = 80; ncs = 5; base = b * 5; }
    else { int u = bid - 100; b = 20 + (u >> 2); t0 = (u & 3) * 100; tlen = 100; ncs = 4; base = 100 + (b - 20) * 4; }

    const int tid = threadIdx.x, lane = tid & 31, wid = tid >> 5;
    float* dqs = (float*)smraw;
    float* ws  = dqs + 1024;
    float* red = ws + 104;
    float* pcr = red + 256;
    int*   flg = (int*)(pcr + 8192);

    const uint4* dqp = (const uint4*)(g_dqb + b * 1024);
    for (int j = tid; j < 128; j += 256) {
        uint4 v = __ldcg(dqp + j);
        const __nv_bfloat162* h = (const __nv_bfloat162*)&v;
#pragma unroll
        for (int k = 0; k < 4; k++) {
            float2 f = __bfloat1622float2(h[k]);
            dqs[j * 8 + k * 2]     = f.x;
            dqs[j * 8 + k * 2 + 1] = f.y;
        }
    }
    __syncthreads();

    const int hl = hlens[b];
    for (int bs = wid * 2; bs < tlen; bs += 16) {
        int t = t0 + bs;
        if (t >= hl) {
            if (lane == 0) { ws[bs] = NEGBIG; ws[bs + 1] = NEGBIG; }
            continue;
        }
        const __nv_bfloat16* r1 = g_preb + ((long long)b * 400 + t) * 1024 + lane * 8;
        const __nv_bfloat16* r2 = r1 + 1024;
        float a1 = 0.f, a2 = 0.f, a3 = 0.f, a4 = 0.f;
#pragma unroll
        for (int q = 0; q < 4; q++) {
            uint4 v1 = *(const uint4*)(r1 + q * 256);
            uint4 v2 = *(const uint4*)(r2 + q * 256);
            const __nv_bfloat162* h1 = (const __nv_bfloat162*)&v1;
            const __nv_bfloat162* h2 = (const __nv_bfloat162*)&v2;
#pragma unroll
            for (int k = 0; k < 4; k++) {
                float2 d = *(const float2*)(dqs + q * 256 + lane * 8 + k * 2);
                float2 f1 = __bfloat1622float2(h1[k]);
                float2 f2 = __bfloat1622float2(h2[k]);
                a1 = fmaf(f1.x, d.x, a1); a2 = fmaf(f1.y, d.y, a2);
                a3 = fmaf(f2.x, d.x, a3); a4 = fmaf(f2.y, d.y, a4);
            }
        }
        float s1 = a1 + a2, s2 = a3 + a4;
#pragma unroll
        for (int off = 16; off; off >>= 1) {
            s1 += __shfl_xor_sync(0xffffffffu, s1, off);
            s2 += __shfl_xor_sync(0xffffffffu, s2, off);
        }
        if (lane == 0) {
            ws[bs]     = 2.f * s1;
            ws[bs + 1] = (t + 1 < hl) ? 2.f * s2 : NEGBIG;
        }
    }
    __syncthreads();

    float lm = NEGBIG;
    for (int i = tid; i < tlen; i += 256) lm = fmaxf(lm, ws[i]);
    red[tid] = lm; __syncthreads();
    for (int st = 128; st; st >>= 1) { if (tid < st) red[tid] = fmaxf(red[tid], red[tid + st]); __syncthreads(); }
    const float m = red[0]; __syncthreads();
    float ls = 0.f;
    for (int i = tid; i < tlen; i += 256) { float w = expf(ws[i] - m); ws[i] = w; ls += w; }
    red[tid] = ls; __syncthreads();
    for (int st = 128; st; st >>= 1) { if (tid < st) red[tid] += red[tid + st]; __syncthreads(); }
    const float sl = red[0];
    __syncthreads();

    float pacc[32];
#pragma unroll
    for (int i = 0; i < 32; i++) pacc[i] = 0.f;
    for (int bs = wid * 2; bs < tlen; bs += 16) {
        if (t0 + bs >= hl) continue;
        float w1 = ws[bs], w2 = ws[bs + 1];
        const __nv_bfloat16* r1 = g_hsb + ((long long)b * 400 + t0 + bs) * 1024 + lane * 8;
        const __nv_bfloat16* r2 = r1 + 1024;
#pragma unroll
        for (int q = 0; q < 4; q++) {
            uint4 v1 = *(const uint4*)(r1 + q * 256);
            uint4 v2 = *(const uint4*)(r2 + q * 256);
            const __nv_bfloat162* h1 = (const __nv_bfloat162*)&v1;
            const __nv_bfloat162* h2 = (const __nv_bfloat162*)&v2;
#pragma unroll
            for (int k = 0; k < 4; k++) {
                float2 f1 = __bfloat1622float2(h1[k]);
                float2 f2 = __bfloat1622float2(h2[k]);
                int o = q * 8 + k * 2;
                pacc[o]     = fmaf(w1, f1.x, fmaf(w2, f2.x, pacc[o]));
                pacc[o + 1] = fmaf(w1, f1.y, fmaf(w2, f2.y, pacc[o + 1]));
            }
        }
    }
#pragma unroll
    for (int q = 0; q < 4; q++)
#pragma unroll
        for (int j = 0; j < 8; j++)
            pcr[wid * 1024 + q * 256 + lane * 8 + j] = pacc[q * 8 + j];
    __syncthreads();
    for (int col = tid; col < 1024; col += 256) {
        float a = 0.f;
#pragma unroll
        for (int w = 0; w < 8; w++) a += pcr[w * 1024 + col];
        g_pc[bid * 1024 + col] = a;
    }
    if (tid == 0) { g_ms[bid * 2] = m; g_ms[bid * 2 + 1] = sl; }
    __syncthreads();

    if (tid == 0) {
        __threadfence();
        unsigned old = atomicAdd(&g_cmb[b], 1u);
        *flg = (old == (unsigned)(s * ncs + ncs - 1)) ? 1 : 0;
    }
    __syncthreads();
    if (*flg) {
        float mi[5], si[5];
        for (int i = 0; i < ncs; i++) {
            mi[i] = __ldcg(&g_ms[(base + i) * 2]);
            si[i] = __ldcg(&g_ms[(base + i) * 2 + 1]);
        }
        float M = NEGBIG;
        for (int i = 0; i < ncs; i++) M = fmaxf(M, mi[i]);
        float sc[5], Ssum = 0.f;
        for (int i = 0; i < ncs; i++) { sc[i] = expf(mi[i] - M); Ssum += sc[i] * si[i]; }
        float inv = 1.f / Ssum;
        for (int col = tid; col < 1024; col += 256) {
            float a = 0.f;
            for (int i = 0; i < ncs; i++) a += sc[i] * __ldcg(&g_pc[(base + i) * 1024 + col]);
            __nv_bfloat16 v = __float2bfloat16(a * inv);
            g_attb[b * 1024 + col] = v;
            g_zallb[((long long)s * 32 + b) * 2048 + 1024 + col] = v;
        }
    }
    __syncthreads();
}

// ---------------------------------------------------------------- main loop
__global__ void __launch_bounds__(256, 1) k_loop(const int* __restrict__ hlens,
                                                 const float* __restrict__ bdec) {
    extern __shared__ char sm[];
    const int bid = blockIdx.x;
    const int tid = threadIdx.x;
    int ep = 0;

    // Pin this block's Wc0x tile (32 rows x K=2048, chunked 8 x [32][264]) in smem.
    if (bid < 128) {
        __nv_bfloat16* pin = (__nv_bfloat16*)sm;
#pragma unroll
        for (int ci = 0; ci < 8; ci++) {
#pragma unroll
            for (int j = 0; j < 4; j++) {
                int u = tid + j * 256;
                int r = u >> 5, c = (u & 31) << 3;
                cpa16(sptr(pin + ci * 8448 + r * 264 + c),
                      g_Wc0x + (long long)(bid * 32 + r) * 2048 + ci * 256 + c);
            }
        }
        CP_COMMIT;
        CP_WAIT0;
    }
    __syncthreads();

    for (int s = 0; s <= 101; s++) {
        const int p = s & 1;
        // Phase 1a: g1(s-1) on 0..127 || dq(s) on 128..143 -> flag
        if (bid < 128) {
            if (s >= 1)
                gtile_g1(sm + PIN, bid * 32, g_Wc1r, g_bs1r,
                         g_z0s[p], g_z1s[1 - p], g_c1, g_z1s[p], g_zallb, s - 1);
        } else if (bid < 144) {
            if (s <= 100) {
                gtile_dq(sm, (bid - 128) * 64, g_Wdecb, bdec, g_z0s[p], g_dqb);
                if (tid == 0) {
                    __threadfence();
                    atomicAdd(&g_dqf, 1u);
                }
            }
        }
        // Phase 1b: wait dq flag, attention on all 148 blocks
        if (s <= 100) {
            if (tid == 0) {
                unsigned r;
                do { asm volatile("ld.global.cg.u32 %0, [%1];" : "=r"(r) : "l"(&g_dqf)); }
                while (r < (unsigned)(16 * (s + 1)));
            }
            __syncthreads();
            phase_epc(sm + PIN, s, hlens);
        }
        gbar(ep); ep++;
        if (s == 101) break;

        // Phase 2: g0(s) from pinned weights
        if (bid < 128) {
            gtile_g0pin(sm, bid * 32, g_attb, g_z0s[p],
                        g_c0, g_z0s[1 - p], s, g_emb0 + (long long)s * 32 * 4096);
        }
        gbar(ep); ep++;
    }
}

// ---------------------------------------------------------------- CE
__global__ void k_ce(const void* __restrict__ ys) {
    int r = blockIdx.x;
    int l = r / BB, b = r % BB;
    const float* y = g_yall + (long long)r * VV;
    __shared__ float red[256];
    int tid = threadIdx.x;
    float lm = NEGBIG;
    for (int v = tid; v < VV; v += 256) lm = fmaxf(lm, y[v]);
    red[tid] = lm; __syncthreads();
    for (int s = 128; s > 0; s >>= 1) { if (tid < s) red[tid] = fmaxf(red[tid], red[tid + s]); __syncthreads(); }
    float m = red[0]; __syncthreads();
    float ls = 0.f;
    for (int v = tid; v < VV; v += 256) ls += expf(y[v] - m);
    red[tid] = ls; __syncthreads();
    for (int s = 128; s > 0; s >>= 1) { if (tid < s) red[tid] += red[tid + s]; __syncthreads(); }
    if (tid == 0) {
        int tgt = (l < LL) ? read_ys(ys, b * LL + l) : 4999;
        atomicAdd(&g_loss, logf(red[0]) + m - y[tgt]);
    }
}

__global__ void k_fin(float* out) {
    out[0] = g_loss * ((float)LL / (float)(L1 * BB));
}

// ---------------------------------------------------------------- launch
extern "C" void kernel_launch(void* const* d_in, const int* in_sizes, int n_in,
                              void* d_out, int out_size) {
    const float* hs    = (const float*)d_in[0];
    const float* embed = (const float*)d_in[1];
    const float* Wenc  = (const float*)d_in[2];
    const float* benc  = (const float*)d_in[3];
    const float* Wdec  = (const float*)d_in[4];
    const float* bdec  = (const float*)d_in[5];
    const float* Wih0  = (const float*)d_in[6];
    const float* Whh0  = (const float*)d_in[7];
    const float* bih0  = (const float*)d_in[8];
    const float* bhh0  = (const float*)d_in[9];
    const float* Wih1  = (const float*)d_in[10];
    const float* Whh1  = (const float*)d_in[11];
    const float* bih1  = (const float*)d_in[12];
    const float* bhh1  = (const float*)d_in[13];
    const float* Wout  = (const float*)d_in[14];
    const float* bout  = (const float*)d_in[15];
    const int*   hlens = (const int*)d_in[16];
    const void*  ys    = (const void*)d_in[17];

    __nv_bfloat16 *hsb, *preb, *eysb, *Wencb, *Woutb, *Wc0e, *zallb;
    float *yall, *bs0r, *emb0;
    cudaGetSymbolAddress((void**)&hsb,   g_hsb);
    cudaGetSymbolAddress((void**)&preb,  g_preb);
    cudaGetSymbolAddress((void**)&eysb,  g_eysb);
    cudaGetSymbolAddress((void**)&Wencb, g_Wencb);
    cudaGetSymbolAddress((void**)&Woutb, g_Woutb);
    cudaGetSymbolAddress((void**)&Wc0e,  g_Wc0e);
    cudaGetSymbolAddress((void**)&zallb, g_zallb);
    cudaGetSymbolAddress((void**)&yall,  g_yall);
    cudaGetSymbolAddress((void**)&bs0r,  g_bs0r);
    cudaGetSymbolAddress((void**)&emb0,  g_emb0);

    static int smem_set = 0;
    if (!smem_set) {
        cudaFuncSetAttribute(k_loop, cudaFuncAttributeMaxDynamicSharedMemorySize, SMSZ);
        cudaFuncSetAttribute(mma_big<0>, cudaFuncAttributeMaxDynamicSharedMemorySize, BIG_SMEM);
        cudaFuncSetAttribute(mma_big<1>, cudaFuncAttributeMaxDynamicSharedMemorySize, BIG_SMEM);
        smem_set = 1;
    }

    k_prep_all<<<296, 256>>>(hs, embed, Wenc, Wdec, Wout,
                             Wih0, Whh0, Wih1, Whh1,
                             bih0, bhh0, bih1, bhh1, ys);

    mma_big<0><<<dim3(4096 / 128, (L1 * BB + 127) / 128), 256, BIG_SMEM>>>(
        eysb, Wc0e, bs0r, emb0, nullptr, L1 * BB, 4096, 1024);

    mma_big<1><<<dim3(DD / 128, BB * TT / 128), 256, BIG_SMEM>>>(
        hsb, Wencb, benc, nullptr, preb, BB * TT, DD, DD);

    k_loop<<<NBLK, 256, SMSZ>>>(hlens, bdec);

    mma_big<0><<<dim3((VV + 127) / 128, (L1 * BB + 127) / 128), 256, BIG_SMEM>>>(
        zallb, Woutb, bout, yall, nullptr, L1 * BB, VV, 2048);

    k_ce<<<L1 * BB, 256>>>(ys);
    k_fin<<<1, 1>>>((float*)d_out);
}

// round 13
// speedup vs baseline: 1.2821x; 1.0697x over previous
#include <cuda_runtime.h>
#include <cuda_bf16.h>

#define BB 32
#define TT 400
#define DD 1024
#define VV 5000
#define LL 100
#define L1 101
#define NEGBIG -1e30f
#define NBLK 148
// smem: pinned Wc0x tile 135168B | stream region 69632B | mbarriers 32B
#define PIN 135168
#define MBAR_OFF 204800
#define SMSZ 204928
#define BIG_SMEM 110592

__device__ __align__(16) __nv_bfloat16 g_hsb [BB * TT * DD];
__device__ __align__(16) __nv_bfloat16 g_preb[BB * TT * DD];
__device__ __align__(16) __nv_bfloat16 g_eysb[L1 * BB * DD];
__device__ __align__(16) __nv_bfloat16 g_Wencb[DD * DD];
__device__ __align__(16) __nv_bfloat16 g_Wdecb[DD * DD];
__device__ __align__(16) __nv_bfloat16 g_Woutb[VV * 2048];
__device__ __align__(16) __nv_bfloat16 g_Wc0e[4096 * 1024];
__device__ __align__(16) __nv_bfloat16 g_Wc0x[4096 * 2048];
// g1 weights, padded chunk layout: [128 tiles][16 chunks][32 rows][136 cols]
__device__ __align__(16) __nv_bfloat16 g_Wc1p[128 * 16 * 32 * 136];
__device__ __align__(16) float g_bs0r[4096];
__device__ __align__(16) float g_bs1r[4096];
__device__ __align__(16) float g_emb0[(long long)L1 * BB * 4096];
__device__ __align__(16) __nv_bfloat16 g_dqb[BB * DD];
__device__ __align__(16) __nv_bfloat16 g_attb[BB * DD];
__device__ __align__(16) __nv_bfloat16 g_z0s[2][BB * DD];
// padded chunk copies for g1 A: [8 chunks][32 b][136]
__device__ __align__(16) __nv_bfloat16 g_z0p[2][8 * 32 * 136];
__device__ __align__(16) __nv_bfloat16 g_z1p[2][8 * 32 * 136];
__device__ __align__(16) float g_c0[BB * DD];
__device__ __align__(16) float g_c1[BB * DD];
__device__ __align__(16) float g_pc[148 * 1024];
__device__ __align__(16) float g_ms[304];
__device__ unsigned g_cmb[32];
__device__ __align__(16) __nv_bfloat16 g_zallb[L1 * BB * 2048];
__device__ __align__(16) float g_yall[(long long)L1 * BB * VV];
__device__ float g_loss;
__device__ int g_i64;
__device__ unsigned g_arrive;
__device__ unsigned g_release;
__device__ unsigned g_dqf;

__device__ __forceinline__ float sigm(float x) { return 1.0f / (1.0f + expf(-x)); }
__device__ __forceinline__ int read_ys(const void* ys, int i) {
    return g_i64 ? (int)((const long long*)ys)[i] : ((const int*)ys)[i];
}
__device__ __forceinline__ unsigned sptr(const void* p) {
    unsigned r;
    asm("{.reg .u64 t; cvta.to.shared.u64 t, %1; cvt.u32.u64 %0, t;}" : "=r"(r) : "l"(p));
    return r;
}
__device__ __forceinline__ void cpa16(unsigned s, const void* g) {
    asm volatile("cp.async.cg.shared.global [%0], [%1], 16;" :: "r"(s), "l"(g));
}
#define CP_COMMIT asm volatile("cp.async.commit_group;")
#define CP_WAIT2  asm volatile("cp.async.wait_group 2;")
#define CP_WAIT1  asm volatile("cp.async.wait_group 1;")
#define CP_WAIT0  asm volatile("cp.async.wait_group 0;")

#define MWAIT(mb, ph) do {                                                          \
    unsigned _done;                                                                 \
    do {                                                                            \
        asm volatile("{.reg .pred p; "                                              \
                     "mbarrier.try_wait.parity.acquire.cta.shared::cta.b64 p, [%1], %2; " \
                     "selp.b32 %0,1,0,p;}"                                          \
                     : "=r"(_done) : "r"(mb), "r"((unsigned)(ph)) : "memory");      \
    } while (!_done);                                                               \
} while (0)

__device__ __forceinline__ unsigned pack2(float a, float b) {
    __nv_bfloat162 p = __floats2bfloat162_rn(a, b);
    return *(unsigned*)&p;
}

// ---------------------------------------------------------------- fused prologue
__global__ void k_prep_all(
    const float* __restrict__ hs, const float* __restrict__ embed,
    const float* __restrict__ Wenc, const float* __restrict__ Wdec,
    const float* __restrict__ Wout,
    const float* __restrict__ Wih0, const float* __restrict__ Whh0,
    const float* __restrict__ Wih1, const float* __restrict__ Whh1,
    const float* __restrict__ bih0, const float* __restrict__ bhh0,
    const float* __restrict__ bih1, const float* __restrict__ bhh1,
    const void* __restrict__ ys)
{
    __shared__ int s_i64;
    const int tid = threadIdx.x;
    if (tid == 0) {
        const int* w = (const int*)ys;
        int f = 1;
        for (int j = 1; j < 64; j += 2) if (w[j] != 0) f = 0;
        s_i64 = f;
    }
    __syncthreads();
    const int i64 = s_i64;
    const long long gi = (long long)blockIdx.x * blockDim.x + tid;
    const long long gn = (long long)gridDim.x * blockDim.x;

    {
        __nv_bfloat16 z = __float2bfloat16(0.f);
        for (long long j = gi; j < BB * DD; j += gn) {
            g_c0[j] = 0.f; g_c1[j] = 0.f;
            g_z0s[0][j] = z; g_z0s[1][j] = z;
        }
        for (long long j = gi; j < 8 * 32 * 136; j += gn) {
            g_z0p[0][j] = z; g_z0p[1][j] = z;
            g_z1p[0][j] = z; g_z1p[1][j] = z;
        }
        for (long long j = gi; j < 4096; j += gn) {
            int u = (int)j >> 2, gate = (int)j & 3;
            int orow = gate * 1024 + u;
            g_bs0r[j] = bih0[orow] + bhh0[orow];
            g_bs1r[j] = bih1[orow] + bhh1[orow];
        }
        if (gi < 32) g_cmb[gi] = 0u;
        if (gi == 0) { g_loss = 0.f; g_arrive = 0u; g_release = 0u; g_dqf = 0u; g_i64 = i64; }
    }
    {
        const float4* s = (const float4*)hs;
        uint4* d = (uint4*)g_hsb;
        for (long long j = gi; j < 1638400LL; j += gn) {
            float4 a = s[2 * j], b = s[2 * j + 1];
            d[j] = make_uint4(pack2(a.x, a.y), pack2(a.z, a.w), pack2(b.x, b.y), pack2(b.z, b.w));
        }
    }
    {
        const float4* s = (const float4*)Wenc;
        uint4* d = (uint4*)g_Wencb;
        for (long long j = gi; j < 131072LL; j += gn) {
            float4 a = s[2 * j], b = s[2 * j + 1];
            d[j] = make_uint4(pack2(a.x, a.y), pack2(a.z, a.w), pack2(b.x, b.y), pack2(b.z, b.w));
        }
    }
    {
        const float4* s = (const float4*)Wdec;
        uint4* d = (uint4*)g_Wdecb;
        for (long long j = gi; j < 131072LL; j += gn) {
            float4 a = s[2 * j], b = s[2 * j + 1];
            d[j] = make_uint4(pack2(a.x, a.y), pack2(a.z, a.w), pack2(b.x, b.y), pack2(b.z, b.w));
        }
    }
    {
        const float4* s = (const float4*)Wout;
        uint4* d = (uint4*)g_Woutb;
        for (long long j = gi; j < 1280000LL; j += gn) {
            float4 a = s[2 * j], b = s[2 * j + 1];
            d[j] = make_uint4(pack2(a.x, a.y), pack2(a.z, a.w), pack2(b.x, b.y), pack2(b.z, b.w));
        }
    }
    {
        for (long long it = gi; it < 413696LL; it += gn) {
            int row = (int)(it >> 7), col = (int)(it & 127);
            int l = row >> 5, b = row & 31;
            int tok = 4999;
            if (l > 0) {
                int idx = b * LL + l - 1;
                tok = i64 ? (int)((const long long*)ys)[idx] : ((const int*)ys)[idx];
            }
            float4 v = ((const float4*)(embed + (long long)tok * 1024))[col];
            ((uint2*)(g_eysb + (long long)row * 1024))[col] = make_uint2(pack2(v.x, v.y), pack2(v.z, v.w));
        }
    }
    {
        for (long long j4 = gi; j4 < 1048576LL; j4 += gn) {
            long long j = j4 * 4;
            int r = (int)(j >> 10), c = (int)(j & 1023);
            long long orow = (r & 3) * 1024 + (r >> 2);
            float4 v = *(const float4*)(Wih0 + orow * 2048 + c);
            *(uint2*)(g_Wc0e + j) = make_uint2(pack2(v.x, v.y), pack2(v.z, v.w));
        }
    }
    {
        for (long long j4 = gi; j4 < 2097152LL; j4 += gn) {
            long long j = j4 * 4;
            int r = (int)(j >> 11), c = (int)(j & 2047);
            long long orow = (r & 3) * 1024 + (r >> 2);
            float4 v = (c < 1024) ? *(const float4*)(Wih0 + orow * 2048 + 1024 + c)
                                  : *(const float4*)(Whh0 + orow * 1024 + (c - 1024));
            *(uint2*)(g_Wc0x + j) = make_uint2(pack2(v.x, v.y), pack2(v.z, v.w));
        }
    }
    // Wc1 padded chunk layout: [tile][kc][r][c], c<128 real (gate-interleaved), 128..135 zero pad
    {
        const long long N4 = 128LL * 16 * 32 * 136 / 4;   // 2228224
        for (long long j4 = gi; j4 < N4; j4 += gn) {
            long long j = j4 * 4;
            int tile = (int)(j / 69632);
            int rem  = (int)(j % 69632);
            int kc = rem / 4352;
            int r  = (rem % 4352) / 136;
            int c  = rem % 136;
            uint2 out = make_uint2(0u, 0u);
            if (c < 128) {
                int rg = tile * 32 + r;
                long long orow = (rg & 3) * 1024 + (rg >> 2);
                int cc = kc * 128 + c;
                float4 v = (cc < 1024) ? *(const float4*)(Wih1 + orow * 1024 + cc)
                                       : *(const float4*)(Whh1 + orow * 1024 + (cc - 1024));
                out = make_uint2(pack2(v.x, v.y), pack2(v.z, v.w));
            }
            *(uint2*)(g_Wc1p + j) = out;
        }
    }
}

__device__ __forceinline__ void mma_bf16(float* d, const unsigned* a, const unsigned* b) {
    asm volatile(
        "mma.sync.aligned.m16n8k16.row.col.f32.bf16.bf16.f32 "
        "{%0,%1,%2,%3}, {%4,%5,%6,%7}, {%8,%9}, {%0,%1,%2,%3};\n"
        : "+f"(d[0]), "+f"(d[1]), "+f"(d[2]), "+f"(d[3])
        : "r"(a[0]), "r"(a[1]), "r"(a[2]), "r"(a[3]), "r"(b[0]), "r"(b[1]));
}

// ---------------------------------------------------------------- big GEMM
#define BKP 72
__device__ __forceinline__ void issue_big(
    char* smb, int slot, int k0,
    const __nv_bfloat16* A, const __nv_bfloat16* B,
    int M, int N, int K, int m0, int n0)
{
    __nv_bfloat16* smA = (__nv_bfloat16*)smb + slot * (2 * 128 * BKP);
    __nv_bfloat16* smB = smA + 128 * BKP;
    const int tid = threadIdx.x;
#pragma unroll
    for (int j = 0; j < 4; j++) {
        int idx = tid + j * 256;
        int r = idx >> 3, c = (idx & 7) * 8;
        int m = m0 + r; if (m >= M) m = 0;
        cpa16(sptr(smA + r * BKP + c), A + (long long)m * K + k0 + c);
        int n = n0 + r; if (n >= N) n = 0;
        cpa16(sptr(smB + r * BKP + c), B + (long long)n * K + k0 + c);
    }
}

template <int EPI>
__global__ __launch_bounds__(256) void mma_big(
    const __nv_bfloat16* __restrict__ A, const __nv_bfloat16* __restrict__ B,
    const float* __restrict__ bias, float* __restrict__ Cf,
    __nv_bfloat16* __restrict__ Cb, int M, int N, int K)
{
    extern __shared__ char smb[];
    const int tid = threadIdx.x, lane = tid & 31, wid = tid >> 5;
    const int wm = wid >> 1, wn = wid & 1;
    const int m0 = blockIdx.y * 128, n0 = blockIdx.x * 128;
    const int g = lane >> 2, tg = lane & 3;
    const int S = K >> 6;

    float acc[2][8][4];
#pragma unroll
    for (int a = 0; a < 2; a++)
#pragma unroll
        for (int b = 0; b < 8; b++)
#pragma unroll
            for (int c = 0; c < 4; c++) acc[a][b][c] = 0.f;

    issue_big(smb, 0, 0, A, B, M, N, K, m0, n0); CP_COMMIT;
    if (S > 1) issue_big(smb, 1, 64, A, B, M, N, K, m0, n0);
    CP_COMMIT;

    for (int si = 0; si < S; si++) {
        CP_WAIT1;
        __syncthreads();
        if (si + 2 < S) issue_big(smb, (si + 2) % 3, (si + 2) << 6, A, B, M, N, K, m0, n0);
        CP_COMMIT;
        __nv_bfloat16 (*As)[BKP] = (__nv_bfloat16(*)[BKP])((__nv_bfloat16*)smb + (si % 3) * (2 * 128 * BKP));
        __nv_bfloat16 (*Bs)[BKP] = (__nv_bfloat16(*)[BKP])((__nv_bfloat16*)smb + (si % 3) * (2 * 128 * BKP) + 128 * BKP);
#pragma unroll
        for (int kt = 0; kt < 4; kt++) {
            const int c0 = kt * 16 + tg * 2;
            unsigned af[2][4];
#pragma unroll
            for (int mt = 0; mt < 2; mt++) {
                int r = wm * 32 + mt * 16 + g;
                af[mt][0] = *(const unsigned*)&As[r][c0];
                af[mt][1] = *(const unsigned*)&As[r + 8][c0];
                af[mt][2] = *(const unsigned*)&As[r][c0 + 8];
                af[mt][3] = *(const unsigned*)&As[r + 8][c0 + 8];
            }
#pragma unroll
            for (int nt = 0; nt < 8; nt++) {
                int n = wn * 64 + nt * 8 + g;
                unsigned bf[2];
                bf[0] = *(const unsigned*)&Bs[n][c0];
                bf[1] = *(const unsigned*)&Bs[n][c0 + 8];
                mma_bf16(acc[0][nt], af[0], bf);
                mma_bf16(acc[1][nt], af[1], bf);
            }
        }
    }

#pragma unroll
    for (int mt = 0; mt < 2; mt++) {
#pragma unroll
        for (int nt = 0; nt < 8; nt++) {
            int r = m0 + wm * 32 + mt * 16 + g;
            int c = n0 + wn * 64 + nt * 8 + tg * 2;
            float* a = acc[mt][nt];
            if (EPI == 0) {
                float b0 = (c < N) ? bias[c] : 0.f;
                float b1 = (c + 1 < N) ? bias[c + 1] : 0.f;
                if (r < M) {
                    if (c < N)     Cf[(long long)r * N + c]     = a[0] + b0;
                    if (c + 1 < N) Cf[(long long)r * N + c + 1] = a[1] + b1;
                }
                if (r + 8 < M) {
                    if (c < N)     Cf[(long long)(r + 8) * N + c]     = a[2] + b0;
                    if (c + 1 < N) Cf[(long long)(r + 8) * N + c + 1] = a[3] + b1;
                }
            } else {
                float b0 = bias[c], b1 = bias[c + 1];
                __nv_bfloat162 v0 = __floats2bfloat162_rn(tanhf(a[0] + b0), tanhf(a[1] + b1));
                __nv_bfloat162 v1 = __floats2bfloat162_rn(tanhf(a[2] + b0), tanhf(a[3] + b1));
                *(__nv_bfloat162*)(Cb + (long long)r * N + c) = v0;
                *(__nv_bfloat162*)(Cb + (long long)(r + 8) * N + c) = v1;
            }
        }
    }
}

// ---------------------------------------------------------------- barrier
__device__ __forceinline__ void gbar(int e) {
    __syncthreads();
    if (threadIdx.x == 0) {
        __threadfence();
        unsigned old = atomicAdd(&g_arrive, 1u);
        if (old == (unsigned)e * NBLK + (NBLK - 1)) {
            atomicExch(&g_release, (unsigned)(e + 1));
        } else {
            unsigned r;
            do { asm volatile("ld.global.cg.u32 %0, [%1];" : "=r"(r) : "l"(&g_release)); }
            while (r < (unsigned)(e + 1));
        }
        __threadfence();
    }
    __syncthreads();
}

// ---------------------------------------------------------------- dq tile GEMM (cp.async, unchanged)
__device__ __forceinline__ void issue_dq(char* smraw, int slot, int kc,
                                         const __nv_bfloat16* A0, const __nv_bfloat16* B, int n0)
{
    constexpr int ASZ = 32 * 264;
    constexpr int STE = ASZ + 64 * 264;
    __nv_bfloat16* smA = (__nv_bfloat16*)smraw + slot * STE;
    __nv_bfloat16* smB = smA + ASZ;
    const int tid = threadIdx.x;
    const int kbase = kc << 8;
#pragma unroll
    for (int j = 0; j < 4; j++) {
        int u = tid + j * 256;
        int r = u >> 5, c = (u & 31) << 3;
        cpa16(sptr(smA + r * 264 + c), A0 + r * 1024 + kbase + c);
    }
#pragma unroll
    for (int j = 0; j < 8; j++) {
        int u = tid + j * 256;
        int r = u >> 5, c = (u & 31) << 3;
        cpa16(sptr(smB + r * 264 + c), B + (long long)(n0 + r) * 1024 + kbase + c);
    }
}

__device__ void gtile_dq(char* smraw, int n0, const __nv_bfloat16* __restrict__ B,
                         const float* __restrict__ bias, const __nv_bfloat16* A0,
                         __nv_bfloat16* outb)
{
    constexpr int ASZ = 32 * 264;
    constexpr int STE = ASZ + 64 * 264;
    constexpr int NW = 32 * 64;
    const int tid = threadIdx.x, lane = tid & 31, wid = tid >> 5;
    const int g = lane >> 2, tg = lane & 3;
    const int S = 4;

    float acc[2][8][4];
#pragma unroll
    for (int a = 0; a < 2; a++)
#pragma unroll
        for (int b = 0; b < 8; b++)
#pragma unroll
            for (int c = 0; c < 4; c++) acc[a][b][c] = 0.f;

#pragma unroll
    for (int st = 0; st < 3; st++) {
        if (st < S) issue_dq(smraw, st, st, A0, B, n0);
        CP_COMMIT;
    }

    for (int si = 0; si < S; si++) {
        CP_WAIT2;
        __syncthreads();
        int nx = si + 3;
        if (nx < S) issue_dq(smraw, nx & 3, nx, A0, B, n0);
        CP_COMMIT;
        __nv_bfloat16 (*As)[264] = (__nv_bfloat16(*)[264])((__nv_bfloat16*)smraw + (si & 3) * STE);
        __nv_bfloat16 (*Bs)[264] = (__nv_bfloat16(*)[264])((__nv_bfloat16*)smraw + (si & 3) * STE + ASZ);
#pragma unroll
        for (int ks = 0; ks < 2; ks++) {
            const int c0 = wid * 32 + ks * 16 + tg * 2;
            unsigned af[2][4];
#pragma unroll
            for (int mt = 0; mt < 2; mt++) {
                int r = mt * 16 + g;
                af[mt][0] = *(const unsigned*)&As[r][c0];
                af[mt][1] = *(const unsigned*)&As[r + 8][c0];
                af[mt][2] = *(const unsigned*)&As[r][c0 + 8];
                af[mt][3] = *(const unsigned*)&As[r + 8][c0 + 8];
            }
#pragma unroll
            for (int nt = 0; nt < 8; nt++) {
                int n = nt * 8 + g;
                unsigned bf[2];
                bf[0] = *(const unsigned*)&Bs[n][c0];
                bf[1] = *(const unsigned*)&Bs[n][c0 + 8];
                mma_bf16(acc[0][nt], af[0], bf);
                mma_bf16(acc[1][nt], af[1], bf);
            }
        }
    }
    __syncthreads();

    float* Pred = (float*)smraw;
    {
        int base = wid * NW;
#pragma unroll
        for (int mt = 0; mt < 2; mt++)
#pragma unroll
            for (int nt = 0; nt < 8; nt++) {
                int r = mt * 16 + g, cl = nt * 8 + tg * 2;
                Pred[base + r * 64 + cl]           = acc[mt][nt][0];
                Pred[base + r * 64 + cl + 1]       = acc[mt][nt][1];
                Pred[base + (r + 8) * 64 + cl]     = acc[mt][nt][2];
                Pred[base + (r + 8) * 64 + cl + 1] = acc[mt][nt][3];
            }
    }
    __syncthreads();

    for (int o = tid; o < NW; o += 256) {
        int r = o >> 6, c = o & 63;
        float sum = 0.f;
#pragma unroll
        for (int w = 0; w < 8; w++) sum += Pred[w * NW + o];
        outb[r * 1024 + n0 + c] = __float2bfloat16(tanhf(sum + bias[n0 + c]));
    }
    __syncthreads();
}

// ---------------------------------------------------------------- g1: bulk-copy + mbarrier pipeline
__device__ __forceinline__ void issue_g1b(char* stream, unsigned mbar0, int kc,
                                          const __nv_bfloat16* z0p, const __nv_bfloat16* z1p,
                                          const __nv_bfloat16* Bw)
{
    unsigned mb = mbar0 + (kc & 3) * 8;
    asm volatile("mbarrier.arrive.expect_tx.shared.b64 _, [%0], %1;"
                 :: "r"(mb), "r"(17408u) : "memory");
    const __nv_bfloat16* asrc = (kc < 8) ? (z0p + kc * 4352) : (z1p + (kc - 8) * 4352);
    unsigned sa = sptr(stream + (kc & 3) * 17408);
    asm volatile("cp.async.bulk.shared::cta.global.mbarrier::complete_tx::bytes [%0], [%1], %2, [%3];"
                 :: "r"(sa), "l"(asrc), "r"(8704u), "r"(mb) : "memory");
    asm volatile("cp.async.bulk.shared::cta.global.mbarrier::complete_tx::bytes [%0], [%1], %2, [%3];"
                 :: "r"(sa + 8704u), "l"(Bw + kc * 4352), "r"(8704u), "r"(mb) : "memory");
}

__device__ void gtile_g1(char* stream, unsigned mbar0, int* par, int tile,
                         const __nv_bfloat16* z0p, const __nv_bfloat16* z1p,
                         float* cst, __nv_bfloat16* z1po, __nv_bfloat16* zallp, int step)
{
    const int tid = threadIdx.x, lane = tid & 31, wid = tid >> 5;
    const int g = lane >> 2, tg = lane & 3;
    const __nv_bfloat16* Bw = g_Wc1p + (long long)tile * 69632;

    float acc[2][4][4];
#pragma unroll
    for (int a = 0; a < 2; a++)
#pragma unroll
        for (int b = 0; b < 4; b++)
#pragma unroll
            for (int c = 0; c < 4; c++) acc[a][b][c] = 0.f;

    if (tid == 0) {
        issue_g1b(stream, mbar0, 0, z0p, z1p, Bw);
        issue_g1b(stream, mbar0, 1, z0p, z1p, Bw);
        issue_g1b(stream, mbar0, 2, z0p, z1p, Bw);
    }

    for (int si = 0; si < 16; si++) {
        {
            unsigned mb = mbar0 + (si & 3) * 8;
            MWAIT(mb, par[si & 3]);
            par[si & 3] ^= 1;
        }
        __syncthreads();
        if (tid == 0 && si + 3 < 16) issue_g1b(stream, mbar0, si + 3, z0p, z1p, Bw);
        __nv_bfloat16 (*As)[136] = (__nv_bfloat16(*)[136])(stream + (si & 3) * 17408);
        __nv_bfloat16 (*Bs)[136] = (__nv_bfloat16(*)[136])(stream + (si & 3) * 17408 + 8704);
        const int c0 = wid * 16 + tg * 2;
        unsigned af[2][4];
#pragma unroll
        for (int mt = 0; mt < 2; mt++) {
            int r = mt * 16 + g;
            af[mt][0] = *(const unsigned*)&As[r][c0];
            af[mt][1] = *(const unsigned*)&As[r + 8][c0];
            af[mt][2] = *(const unsigned*)&As[r][c0 + 8];
            af[mt][3] = *(const unsigned*)&As[r + 8][c0 + 8];
        }
#pragma unroll
        for (int nt = 0; nt < 4; nt++) {
            int n = nt * 8 + g;
            unsigned bf[2];
            bf[0] = *(const unsigned*)&Bs[n][c0];
            bf[1] = *(const unsigned*)&Bs[n][c0 + 8];
            mma_bf16(acc[0][nt], af[0], bf);
            mma_bf16(acc[1][nt], af[1], bf);
        }
    }
    __syncthreads();

    float* Pred = (float*)stream;
    {
        int base = wid * 1024;
#pragma unroll
        for (int mt = 0; mt < 2; mt++)
#pragma unroll
            for (int nt = 0; nt < 4; nt++) {
                int r = mt * 16 + g, cl = nt * 8 + tg * 2;
                Pred[base + r * 32 + cl]           = acc[mt][nt][0];
                Pred[base + r * 32 + cl + 1]       = acc[mt][nt][1];
                Pred[base + (r + 8) * 32 + cl]     = acc[mt][nt][2];
                Pred[base + (r + 8) * 32 + cl + 1] = acc[mt][nt][3];
            }
    }
    __syncthreads();
    {
        const int n0 = tile * 32;
        int b = tid >> 3, ul = tid & 7;
        float gv[4];
#pragma unroll
        for (int gate = 0; gate < 4; gate++) {
            int col = ul * 4 + gate;
            float sum = 0.f;
#pragma unroll
            for (int w = 0; w < 8; w++) sum += Pred[w * 1024 + b * 32 + col];
            gv[gate] = sum + g_bs1r[n0 + col];
        }
        int u = (n0 >> 2) + ul;
        int gid = b * 1024 + u;
        float cv = sigm(gv[1]) * cst[gid] + sigm(gv[0]) * tanhf(gv[2]);
        float h = sigm(gv[3]) * tanhf(cv);
        cst[gid] = cv;
        z1po[(u >> 7) * 4352 + b * 136 + (u & 127)] = __float2bfloat16(h);
        zallp[(long long)(step * 32 + b) * 2048 + u] = __float2bfloat16(h);
    }
    __syncthreads();
}

// ---------------------------------------------------------------- g0 (B pinned, A cp.async)
__device__ __forceinline__ void issue_g0a(char* strm, int slot, int kc,
                                          const __nv_bfloat16* A0, const __nv_bfloat16* A1)
{
    __nv_bfloat16* smA = (__nv_bfloat16*)strm + slot * (32 * 264);
    const int tid = threadIdx.x;
    const int kbase = kc << 8;
    const int region = kbase >> 10;
    const int koff = kbase & 1023;
#pragma unroll
    for (int j = 0; j < 4; j++) {
        int u = tid + j * 256;
        int r = u >> 5, c = (u & 31) << 3;
        const __nv_bfloat16* src = (region == 0 ? A0 : A1) + r * 1024 + koff + c;
        cpa16(sptr(smA + r * 264 + c), src);
    }
}

__device__ void gtile_g0pin(char* sm, int n0,
                            const __nv_bfloat16* A0, const __nv_bfloat16* A1,
                            float* cst, __nv_bfloat16* znew, __nv_bfloat16* z0po,
                            int step, const float* eb)
{
    char* strm = sm + PIN;
    const int tid = threadIdx.x, lane = tid & 31, wid = tid >> 5;
    const int g = lane >> 2, tg = lane & 3;
    const int S = 8;

    float acc[2][4][4];
#pragma unroll
    for (int a = 0; a < 2; a++)
#pragma unroll
        for (int b = 0; b < 4; b++)
#pragma unroll
            for (int c = 0; c < 4; c++) acc[a][b][c] = 0.f;

#pragma unroll
    for (int st = 0; st < 3; st++) {
        issue_g0a(strm, st, st, A0, A1);
        CP_COMMIT;
    }

    for (int si = 0; si < S; si++) {
        CP_WAIT2;
        __syncthreads();
        int nx = si + 3;
        if (nx < S) issue_g0a(strm, nx & 3, nx, A0, A1);
        CP_COMMIT;
        __nv_bfloat16 (*As)[264] = (__nv_bfloat16(*)[264])((__nv_bfloat16*)strm + (si & 3) * (32 * 264));
        __nv_bfloat16 (*Bs)[264] = (__nv_bfloat16(*)[264])((__nv_bfloat16*)sm + si * (32 * 264));
#pragma unroll
        for (int ks = 0; ks < 2; ks++) {
            const int c0 = wid * 32 + ks * 16 + tg * 2;
            unsigned af[2][4];
#pragma unroll
            for (int mt = 0; mt < 2; mt++) {
                int r = mt * 16 + g;
                af[mt][0] = *(const unsigned*)&As[r][c0];
                af[mt][1] = *(const unsigned*)&As[r + 8][c0];
                af[mt][2] = *(const unsigned*)&As[r][c0 + 8];
                af[mt][3] = *(const unsigned*)&As[r + 8][c0 + 8];
            }
#pragma unroll
            for (int nt = 0; nt < 4; nt++) {
                int n = nt * 8 + g;
                unsigned bf[2];
                bf[0] = *(const unsigned*)&Bs[n][c0];
                bf[1] = *(const unsigned*)&Bs[n][c0 + 8];
                mma_bf16(acc[0][nt], af[0], bf);
                mma_bf16(acc[1][nt], af[1], bf);
            }
        }
    }
    __syncthreads();

    float* Pred = (float*)strm;
    {
        int base = wid * 1024;
#pragma unroll
        for (int mt = 0; mt < 2; mt++)
#pragma unroll
            for (int nt = 0; nt < 4; nt++) {
                int r = mt * 16 + g, cl = nt * 8 + tg * 2;
                Pred[base + r * 32 + cl]           = acc[mt][nt][0];
                Pred[base + r * 32 + cl + 1]       = acc[mt][nt][1];
                Pred[base + (r + 8) * 32 + cl]     = acc[mt][nt][2];
                Pred[base + (r + 8) * 32 + cl + 1] = acc[mt][nt][3];
            }
    }
    __syncthreads();
    {
        int b = tid >> 3, ul = tid & 7;
        float gv[4];
#pragma unroll
        for (int gate = 0; gate < 4; gate++) {
            int col = ul * 4 + gate;
            float sum = 0.f;
#pragma unroll
            for (int w = 0; w < 8; w++) sum += Pred[w * 1024 + b * 32 + col];
            gv[gate] = sum + eb[b * 4096 + n0 + col];
        }
        int u = (n0 >> 2) + ul;
        int gid = b * 1024 + u;
        float cv = sigm(gv[1]) * cst[gid] + sigm(gv[0]) * tanhf(gv[2]);
        float h = sigm(gv[3]) * tanhf(cv);
        cst[gid] = cv;
        __nv_bfloat16 hb = __float2bfloat16(h);
        znew[gid] = hb;
        z0po[(u >> 7) * 4352 + b * 136 + (u & 127)] = hb;
    }
    __syncthreads();
}

// ---------------------------------------------------------------- attention (hlen-skip)
__device__ void phase_epc(char* smraw, int s, const int* __restrict__ hlens) {
    const int bid = blockIdx.x;
    int b, t0, tlen, ncs, base;
    if (bid < 100) { b = bid / 5; t0 = (bid % 5) * 80; tlen = 80; ncs = 5; base = b * 5; }
    else { int u = bid - 100; b = 20 + (u >> 2); t0 = (u & 3) * 100; tlen = 100; ncs = 4; base = 100 + (b - 20) * 4; }

    const int tid = threadIdx.x, lane = tid & 31, wid = tid >> 5;
    float* dqs = (float*)smraw;
    float* ws  = dqs + 1024;
    float* red = ws + 104;
    float* pcr = red + 256;
    int*   flg = (int*)(pcr + 8192);

    const uint4* dqp = (const uint4*)(g_dqb + b * 1024);
    for (int j = tid; j < 128; j += 256) {
        uint4 v = __ldcg(dqp + j);
        const __nv_bfloat162* h = (const __nv_bfloat162*)&v;
#pragma unroll
        for (int k = 0; k < 4; k++) {
            float2 f = __bfloat1622float2(h[k]);
            dqs[j * 8 + k * 2]     = f.x;
            dqs[j * 8 + k * 2 + 1] = f.y;
        }
    }
    __syncthreads();

    const int hl = hlens[b];
    for (int bs = wid * 2; bs < tlen; bs += 16) {
        int t = t0 + bs;
        if (t >= hl) {
            if (lane == 0) { ws[bs] = NEGBIG; ws[bs + 1] = NEGBIG; }
            continue;
        }
        const __nv_bfloat16* r1 = g_preb + ((long long)b * 400 + t) * 1024 + lane * 8;
        const __nv_bfloat16* r2 = r1 + 1024;
        float a1 = 0.f, a2 = 0.f, a3 = 0.f, a4 = 0.f;
#pragma unroll
        for (int q = 0; q < 4; q++) {
            uint4 v1 = *(const uint4*)(r1 + q * 256);
            uint4 v2 = *(const uint4*)(r2 + q * 256);
            const __nv_bfloat162* h1 = (const __nv_bfloat162*)&v1;
            const __nv_bfloat162* h2 = (const __nv_bfloat162*)&v2;
#pragma unroll
            for (int k = 0; k < 4; k++) {
                float2 d = *(const float2*)(dqs + q * 256 + lane * 8 + k * 2);
                float2 f1 = __bfloat1622float2(h1[k]);
                float2 f2 = __bfloat1622float2(h2[k]);
                a1 = fmaf(f1.x, d.x, a1); a2 = fmaf(f1.y, d.y, a2);
                a3 = fmaf(f2.x, d.x, a3); a4 = fmaf(f2.y, d.y, a4);
            }
        }
        float s1 = a1 + a2, s2 = a3 + a4;
#pragma unroll
        for (int off = 16; off; off >>= 1) {
            s1 += __shfl_xor_sync(0xffffffffu, s1, off);
            s2 += __shfl_xor_sync(0xffffffffu, s2, off);
        }
        if (lane == 0) {
            ws[bs]     = 2.f * s1;
            ws[bs + 1] = (t + 1 < hl) ? 2.f * s2 : NEGBIG;
        }
    }
    __syncthreads();

    float lm = NEGBIG;
    for (int i = tid; i < tlen; i += 256) lm = fmaxf(lm, ws[i]);
    red[tid] = lm; __syncthreads();
    for (int st = 128; st; st >>= 1) { if (tid < st) red[tid] = fmaxf(red[tid], red[tid + st]); __syncthreads(); }
    const float m = red[0]; __syncthreads();
    float ls = 0.f;
    for (int i = tid; i < tlen; i += 256) { float w = expf(ws[i] - m); ws[i] = w; ls += w; }
    red[tid] = ls; __syncthreads();
    for (int st = 128; st; st >>= 1) { if (tid < st) red[tid] += red[tid + st]; __syncthreads(); }
    const float sl = red[0];
    __syncthreads();

    float pacc[32];
#pragma unroll
    for (int i = 0; i < 32; i++) pacc[i] = 0.f;
    for (int bs = wid * 2; bs < tlen; bs += 16) {
        if (t0 + bs >= hl) continue;
        float w1 = ws[bs], w2 = ws[bs + 1];
        const __nv_bfloat16* r1 = g_hsb + ((long long)b * 400 + t0 + bs) * 1024 + lane * 8;
        const __nv_bfloat16* r2 = r1 + 1024;
#pragma unroll
        for (int q = 0; q < 4; q++) {
            uint4 v1 = *(const uint4*)(r1 + q * 256);
            uint4 v2 = *(const uint4*)(r2 + q * 256);
            const __nv_bfloat162* h1 = (const __nv_bfloat162*)&v1;
            const __nv_bfloat162* h2 = (const __nv_bfloat162*)&v2;
#pragma unroll
            for (int k = 0; k < 4; k++) {
                float2 f1 = __bfloat1622float2(h1[k]);
                float2 f2 = __bfloat1622float2(h2[k]);
                int o = q * 8 + k * 2;
                pacc[o]     = fmaf(w1, f1.x, fmaf(w2, f2.x, pacc[o]));
                pacc[o + 1] = fmaf(w1, f1.y, fmaf(w2, f2.y, pacc[o + 1]));
            }
        }
    }
#pragma unroll
    for (int q = 0; q < 4; q++)
#pragma unroll
        for (int j = 0; j < 8; j++)
            pcr[wid * 1024 + q * 256 + lane * 8 + j] = pacc[q * 8 + j];
    __syncthreads();
    for (int col = tid; col < 1024; col += 256) {
        float a = 0.f;
#pragma unroll
        for (int w = 0; w < 8; w++) a += pcr[w * 1024 + col];
        g_pc[bid * 1024 + col] = a;
    }
    if (tid == 0) { g_ms[bid * 2] = m; g_ms[bid * 2 + 1] = sl; }
    __syncthreads();

    if (tid == 0) {
        __threadfence();
        unsigned old = atomicAdd(&g_cmb[b], 1u);
        *flg = (old == (unsigned)(s * ncs + ncs - 1)) ? 1 : 0;
    }
    __syncthreads();
    if (*flg) {
        float mi[5], si[5];
        for (int i = 0; i < ncs; i++) {
            mi[i] = __ldcg(&g_ms[(base + i) * 2]);
            si[i] = __ldcg(&g_ms[(base + i) * 2 + 1]);
        }
        float M = NEGBIG;
        for (int i = 0; i < ncs; i++) M = fmaxf(M, mi[i]);
        float sc[5], Ssum = 0.f;
        for (int i = 0; i < ncs; i++) { sc[i] = expf(mi[i] - M); Ssum += sc[i] * si[i]; }
        float inv = 1.f / Ssum;
        for (int col = tid; col < 1024; col += 256) {
            float a = 0.f;
            for (int i = 0; i < ncs; i++) a += sc[i] * __ldcg(&g_pc[(base + i) * 1024 + col]);
            __nv_bfloat16 v = __float2bfloat16(a * inv);
            g_attb[b * 1024 + col] = v;
            g_zallb[((long long)s * 32 + b) * 2048 + 1024 + col] = v;
        }
    }
    __syncthreads();
}

// ---------------------------------------------------------------- main loop
__global__ void __launch_bounds__(256, 1) k_loop(const int* __restrict__ hlens,
                                                 const float* __restrict__ bdec) {
    extern __shared__ char sm[];
    const int bid = blockIdx.x;
    const int tid = threadIdx.x;
    int ep = 0;
    unsigned mb0 = 0;
    int par[4] = {0, 0, 0, 0};

    if (bid < 128) {
        mb0 = sptr(sm + MBAR_OFF);
        if (tid == 0) {
#pragma unroll
            for (int i = 0; i < 4; i++)
                asm volatile("mbarrier.init.shared.b64 [%0], %1;" :: "r"(mb0 + i * 8), "r"(1u) : "memory");
            asm volatile("fence.proxy.async.shared::cta;" ::: "memory");
        }
        // Pin this block's Wc0x tile (32 rows x K=2048, chunked 8 x [32][264]) in smem.
        __nv_bfloat16* pin = (__nv_bfloat16*)sm;
#pragma unroll
        for (int ci = 0; ci < 8; ci++) {
#pragma unroll
            for (int j = 0; j < 4; j++) {
                int u = tid + j * 256;
                int r = u >> 5, c = (u & 31) << 3;
                cpa16(sptr(pin + ci * 8448 + r * 264 + c),
                      g_Wc0x + (long long)(bid * 32 + r) * 2048 + ci * 256 + c);
            }
        }
        CP_COMMIT;
        CP_WAIT0;
    }
    __syncthreads();

    for (int s = 0; s <= 101; s++) {
        const int p = s & 1;
        // Phase 1a: g1(s-1) on 0..127 || dq(s) on 128..143 -> flag
        if (bid < 128) {
            if (s >= 1)
                gtile_g1(sm + PIN, mb0, par, bid,
                         g_z0p[p], g_z1p[1 - p],
                         g_c1, g_z1p[p], g_zallb, s - 1);
        } else if (bid < 144) {
            if (s <= 100) {
                gtile_dq(sm, (bid - 128) * 64, g_Wdecb, bdec, g_z0s[p], g_dqb);
                if (tid == 0) {
                    __threadfence();
                    atomicAdd(&g_dqf, 1u);
                }
            }
        }
        // Phase 1b: wait dq flag, attention on all 148 blocks
        if (s <= 100) {
            if (tid == 0) {
                unsigned r;
                do { asm volatile("ld.global.cg.u32 %0, [%1];" : "=r"(r) : "l"(&g_dqf)); }
                while (r < (unsigned)(16 * (s + 1)));
            }
            __syncthreads();
            phase_epc(sm + PIN, s, hlens);
        }
        gbar(ep); ep++;
        if (s == 101) break;

        // Phase 2: g0(s) from pinned weights
        if (bid < 128) {
            gtile_g0pin(sm, bid * 32, g_attb, g_z0s[p],
                        g_c0, g_z0s[1 - p], g_z0p[1 - p], s,
                        g_emb0 + (long long)s * 32 * 4096);
        }
        gbar(ep); ep++;
    }
}

// ---------------------------------------------------------------- CE
__global__ void k_ce(const void* __restrict__ ys) {
    int r = blockIdx.x;
    int l = r / BB, b = r % BB;
    const float* y = g_yall + (long long)r * VV;
    __shared__ float red[256];
    int tid = threadIdx.x;
    float lm = NEGBIG;
    for (int v = tid; v < VV; v += 256) lm = fmaxf(lm, y[v]);
    red[tid] = lm; __syncthreads();
    for (int s = 128; s > 0; s >>= 1) { if (tid < s) red[tid] = fmaxf(red[tid], red[tid + s]); __syncthreads(); }
    float m = red[0]; __syncthreads();
    float ls = 0.f;
    for (int v = tid; v < VV; v += 256) ls += expf(y[v] - m);
    red[tid] = ls; __syncthreads();
    for (int s = 128; s > 0; s >>= 1) { if (tid < s) red[tid] += red[tid + s]; __syncthreads(); }
    if (tid == 0) {
        int tgt = (l < LL) ? read_ys(ys, b * LL + l) : 4999;
        atomicAdd(&g_loss, logf(red[0]) + m - y[tgt]);
    }
}

__global__ void k_fin(float* out) {
    out[0] = g_loss * ((float)LL / (float)(L1 * BB));
}

// ---------------------------------------------------------------- launch
extern "C" void kernel_launch(void* const* d_in, const int* in_sizes, int n_in,
                              void* d_out, int out_size) {
    const float* hs    = (const float*)d_in[0];
    const float* embed = (const float*)d_in[1];
    const float* Wenc  = (const float*)d_in[2];
    const float* benc  = (const float*)d_in[3];
    const float* Wdec  = (const float*)d_in[4];
    const float* bdec  = (const float*)d_in[5];
    const float* Wih0  = (const float*)d_in[6];
    const float* Whh0  = (const float*)d_in[7];
    const float* bih0  = (const float*)d_in[8];
    const float* bhh0  = (const float*)d_in[9];
    const float* Wih1  = (const float*)d_in[10];
    const float* Whh1  = (const float*)d_in[11];
    const float* bih1  = (const float*)d_in[12];
    const float* bhh1  = (const float*)d_in[13];
    const float* Wout  = (const float*)d_in[14];
    const float* bout  = (const float*)d_in[15];
    const int*   hlens = (const int*)d_in[16];
    const void*  ys    = (const void*)d_in[17];

    __nv_bfloat16 *hsb, *preb, *eysb, *Wencb, *Woutb, *Wc0e, *zallb;
    float *yall, *bs0r, *emb0;
    cudaGetSymbolAddress((void**)&hsb,   g_hsb);
    cudaGetSymbolAddress((void**)&preb,  g_preb);
    cudaGetSymbolAddress((void**)&eysb,  g_eysb);
    cudaGetSymbolAddress((void**)&Wencb, g_Wencb);
    cudaGetSymbolAddress((void**)&Woutb, g_Woutb);
    cudaGetSymbolAddress((void**)&Wc0e,  g_Wc0e);
    cudaGetSymbolAddress((void**)&zallb, g_zallb);
    cudaGetSymbolAddress((void**)&yall,  g_yall);
    cudaGetSymbolAddress((void**)&bs0r,  g_bs0r);
    cudaGetSymbolAddress((void**)&emb0,  g_emb0);

    static int smem_set = 0;
    if (!smem_set) {
        cudaFuncSetAttribute(k_loop, cudaFuncAttributeMaxDynamicSharedMemorySize, SMSZ);
        cudaFuncSetAttribute(mma_big<0>, cudaFuncAttributeMaxDynamicSharedMemorySize, BIG_SMEM);
        cudaFuncSetAttribute(mma_big<1>, cudaFuncAttributeMaxDynamicSharedMemorySize, BIG_SMEM);
        smem_set = 1;
    }

    k_prep_all<<<296, 256>>>(hs, embed, Wenc, Wdec, Wout,
                             Wih0, Whh0, Wih1, Whh1,
                             bih0, bhh0, bih1, bhh1, ys);

    mma_big<0><<<dim3(4096 / 128, (L1 * BB + 127) / 128), 256, BIG_SMEM>>>(
        eysb, Wc0e, bs0r, emb0, nullptr, L1 * BB, 4096, 1024);

    mma_big<1><<<dim3(DD / 128, BB * TT / 128), 256, BIG_SMEM>>>(
        hsb, Wencb, benc, nullptr, preb, BB * TT, DD, DD);

    k_loop<<<NBLK, 256, SMSZ>>>(hlens, bdec);

    mma_big<0><<<dim3((VV + 127) / 128, (L1 * BB + 127) / 128), 256, BIG_SMEM>>>(
        zallb, Woutb, bout, yall, nullptr, L1 * BB, VV, 2048);

    k_ce<<<L1 * BB, 256>>>(ys);
    k_fin<<<1, 1>>>((float*)d_out);
}